// round 1
// baseline (speedup 1.0000x reference)
#include <cuda_runtime.h>
#include <math_constants.h>

// Problem constants
namespace {
constexpr int Bx  = 2;
constexpr int T   = 1024;
constexpr int D   = 1024;
constexpr int H   = 16;
constexpr int Lx  = 6;
constexpr int DH  = 64;       // D / H
constexpr int DFF = 2048;     // 2 * D
constexpr int MR  = Bx * T;   // 2048 rows
constexpr int D3  = 3 * D;    // 3072
}

// Scratch (device globals: allocation-free per harness rules)
__device__ float g_x  [MR * D];                       //  8 MB residual stream
__device__ float g_h  [MR * D];                       //  8 MB ln-out / attn-out
__device__ float g_qkv[MR * D3];                      // 24 MB
__device__ float g_ffn[MR * DFF];                     // 16 MB
__device__ float g_sc [(size_t)Bx * H * T * T];       // 128 MB scores/probs

// ---------------------------------------------------------------------------
// Embedding: x[b,t,:] = token_emb[ids[b,t],:] + pos_emb[t,:]
// ---------------------------------------------------------------------------
__global__ __launch_bounds__(256) void embed_kernel(
    const int* __restrict__ ids, const float* __restrict__ tok,
    const float* __restrict__ pos, float* __restrict__ x)
{
    const int row = blockIdx.x;           // b*T + t
    const int t   = row & (T - 1);
    const int id  = ids[row];
    const float4* te = (const float4*)(tok + (size_t)id * D);
    const float4* pe = (const float4*)(pos + (size_t)t  * D);
    float4*       xr = (float4*)(x + (size_t)row * D);
    const int c = threadIdx.x;            // 256 threads * float4 = 1024
    float4 a = te[c], b = pe[c];
    xr[c] = make_float4(a.x + b.x, a.y + b.y, a.z + b.z, a.w + b.w);
}

// ---------------------------------------------------------------------------
// LayerNorm (biased variance, eps 1e-5): block per row, 256 threads x 4 elems
// ---------------------------------------------------------------------------
__global__ __launch_bounds__(256) void ln_kernel(
    const float* __restrict__ x, const float* __restrict__ s,
    const float* __restrict__ b, float* __restrict__ out)
{
    const int row = blockIdx.x;
    const int tid = threadIdx.x;
    const float4 v = ((const float4*)(x + (size_t)row * D))[tid];

    __shared__ float r1[256], r2[256];
    float sum = v.x + v.y + v.z + v.w;
    float sq  = v.x * v.x + v.y * v.y + v.z * v.z + v.w * v.w;
    r1[tid] = sum; r2[tid] = sq;
    __syncthreads();
    #pragma unroll
    for (int st = 128; st > 0; st >>= 1) {
        if (tid < st) { r1[tid] += r1[tid + st]; r2[tid] += r2[tid + st]; }
        __syncthreads();
    }
    const float mean = r1[0] * (1.0f / D);
    const float var  = r2[0] * (1.0f / D) - mean * mean;
    const float rstd = rsqrtf(var + 1e-5f);

    const float4 sv = ((const float4*)s)[tid];
    const float4 bv = ((const float4*)b)[tid];
    float4 o;
    o.x = (v.x - mean) * rstd * sv.x + bv.x;
    o.y = (v.y - mean) * rstd * sv.y + bv.y;
    o.z = (v.z - mean) * rstd * sv.z + bv.z;
    o.w = (v.w - mean) * rstd * sv.w + bv.w;
    ((float4*)(out + (size_t)row * D))[tid] = o;
}

// ---------------------------------------------------------------------------
// GEMM: C = A(M x K) * B(K x N), both row-major. 128x128x16 tiles, 8x8/thread.
// EPI: 0 = plain store, 1 = exact GELU, 2 = C = R + acc (residual add)
// All dims divisible by 128/16 for this problem -> no bounds checks.
// ---------------------------------------------------------------------------
template <int EPI>
__global__ __launch_bounds__(256) void gemm_kernel(
    const float* __restrict__ A, const float* __restrict__ Bw,
    const float* __restrict__ R, float* __restrict__ C,
    int Mdim, int Ndim, int Kdim)
{
    constexpr int BM = 128, BN = 128, BK = 16;
    __shared__ float As[BK][BM];   // transposed A tile
    __shared__ float Bs[BK][BN];

    const int tid  = threadIdx.x;
    const int tx   = tid & 15, ty = tid >> 4;
    const int row0 = blockIdx.y * BM;
    const int col0 = blockIdx.x * BN;

    const int aRow = tid >> 2;           // 0..63
    const int aCol = (tid & 3) << 2;     // 0,4,8,12
    const int bRow = tid >> 5;           // 0..7
    const int bCol = (tid & 31) << 2;    // 0..124

    const float* Ap  = A  + (size_t)(row0 + aRow) * Kdim + aCol;
    const float* Ap2 = Ap + (size_t)64 * Kdim;
    const float* Bp  = Bw + (size_t)bRow * Ndim + col0 + bCol;
    const float* Bp2 = Bp + (size_t)8 * Ndim;

    float acc[8][8] = {};

    for (int k0 = 0; k0 < Kdim; k0 += BK) {
        const float4 a0 = *(const float4*)(Ap  + k0);
        const float4 a1 = *(const float4*)(Ap2 + k0);
        const float4 b0 = *(const float4*)(Bp  + (size_t)k0 * Ndim);
        const float4 b1 = *(const float4*)(Bp2 + (size_t)k0 * Ndim);

        As[aCol + 0][aRow]      = a0.x; As[aCol + 1][aRow]      = a0.y;
        As[aCol + 2][aRow]      = a0.z; As[aCol + 3][aRow]      = a0.w;
        As[aCol + 0][aRow + 64] = a1.x; As[aCol + 1][aRow + 64] = a1.y;
        As[aCol + 2][aRow + 64] = a1.z; As[aCol + 3][aRow + 64] = a1.w;
        *(float4*)&Bs[bRow][bCol]     = b0;
        *(float4*)&Bs[bRow + 8][bCol] = b1;
        __syncthreads();

        #pragma unroll
        for (int k = 0; k < BK; k++) {
            float a[8], b[8];
            *(float4*)&a[0] = *(const float4*)&As[k][ty * 8];
            *(float4*)&a[4] = *(const float4*)&As[k][ty * 8 + 4];
            *(float4*)&b[0] = *(const float4*)&Bs[k][tx * 8];
            *(float4*)&b[4] = *(const float4*)&Bs[k][tx * 8 + 4];
            #pragma unroll
            for (int i = 0; i < 8; i++)
                #pragma unroll
                for (int j = 0; j < 8; j++)
                    acc[i][j] += a[i] * b[j];
        }
        __syncthreads();
    }

    #pragma unroll
    for (int i = 0; i < 8; i++) {
        const int r = row0 + ty * 8 + i;
        float* crow = C + (size_t)r * Ndim + col0 + tx * 8;
        const float* rrow = (EPI == 2) ? (R + (size_t)r * Ndim + col0 + tx * 8)
                                       : nullptr;
        #pragma unroll
        for (int j = 0; j < 8; j++) {
            float v = acc[i][j];
            if (EPI == 1) v = 0.5f * v * (1.0f + erff(v * 0.70710678118654752f));
            if (EPI == 2) v += rrow[j];
            crow[j] = v;
        }
    }
}

// ---------------------------------------------------------------------------
// Scores: S[bh, i, j] = (Q_i . K_j) / 8, 64x64 tiles, upper-tri tiles skipped
// ---------------------------------------------------------------------------
__global__ __launch_bounds__(256) void scores_kernel(
    const float* __restrict__ qkv, float* __restrict__ sc)
{
    const int jt = blockIdx.x, it = blockIdx.y;
    if (jt > it) return;                     // fully masked tile, never read
    const int bh = blockIdx.z, b = bh >> 4, h = bh & 15;

    __shared__ float Qs[64][64];             // [k][row]
    __shared__ float Ks[64][64];             // [k][col]
    const int tid = threadIdx.x;

    const size_t qbase = ((size_t)b * T + it * 64) * D3 + h * DH;
    const size_t kbase = ((size_t)b * T + jt * 64) * D3 + D + h * DH;

    #pragma unroll
    for (int i = 0; i < 4; i++) {
        const int f = tid + i * 256;
        const int r = f >> 4, c4 = (f & 15) << 2;
        const float4 q = *(const float4*)(qkv + qbase + (size_t)r * D3 + c4);
        Qs[c4 + 0][r] = q.x; Qs[c4 + 1][r] = q.y;
        Qs[c4 + 2][r] = q.z; Qs[c4 + 3][r] = q.w;
        const float4 kk = *(const float4*)(qkv + kbase + (size_t)r * D3 + c4);
        Ks[c4 + 0][r] = kk.x; Ks[c4 + 1][r] = kk.y;
        Ks[c4 + 2][r] = kk.z; Ks[c4 + 3][r] = kk.w;
    }
    __syncthreads();

    const int tx = tid & 15, ty = tid >> 4;
    float acc[4][4] = {};
    #pragma unroll
    for (int k = 0; k < 64; k++) {
        float a[4], bb[4];
        *(float4*)a  = *(const float4*)&Qs[k][ty * 4];
        *(float4*)bb = *(const float4*)&Ks[k][tx * 4];
        #pragma unroll
        for (int i = 0; i < 4; i++)
            #pragma unroll
            for (int j = 0; j < 4; j++)
                acc[i][j] += a[i] * bb[j];
    }

    float* out = sc + (size_t)bh * T * T + (size_t)(it * 64) * T + jt * 64;
    #pragma unroll
    for (int i = 0; i < 4; i++)
        #pragma unroll
        for (int j = 0; j < 4; j++)
            out[(size_t)(ty * 4 + i) * T + tx * 4 + j] = acc[i][j] * 0.125f;
}

// ---------------------------------------------------------------------------
// Causal softmax, in place. Block per (bh, i). Writes zeros for j > i.
// ---------------------------------------------------------------------------
__global__ __launch_bounds__(256) void softmax_kernel(float* __restrict__ sc)
{
    const int g = blockIdx.x;                // bh*T + i
    const int i = g & (T - 1);
    const int n = i + 1;
    float* row = sc + (size_t)g * T;
    const int tid = threadIdx.x;
    __shared__ float red[256];

    float m = -CUDART_INF_F;
    for (int j = tid; j < n; j += 256) m = fmaxf(m, row[j]);
    red[tid] = m; __syncthreads();
    #pragma unroll
    for (int st = 128; st > 0; st >>= 1) {
        if (tid < st) red[tid] = fmaxf(red[tid], red[tid + st]);
        __syncthreads();
    }
    m = red[0];
    __syncthreads();

    float sum = 0.f;
    for (int j = tid; j < n; j += 256) {
        const float e = expf(row[j] - m);
        row[j] = e;
        sum += e;
    }
    red[tid] = sum; __syncthreads();
    #pragma unroll
    for (int st = 128; st > 0; st >>= 1) {
        if (tid < st) red[tid] += red[tid + st];
        __syncthreads();
    }
    const float inv = 1.0f / red[0];

    for (int j = tid; j < T; j += 256)
        row[j] = (j < n) ? row[j] * inv : 0.0f;
}

// ---------------------------------------------------------------------------
// O = P * V per (bh). 64 query rows x 64 head dims, K-loop stops at causal edge
// ---------------------------------------------------------------------------
__global__ __launch_bounds__(256) void attnv_kernel(
    const float* __restrict__ sc, const float* __restrict__ qkv,
    float* __restrict__ o)
{
    const int it = blockIdx.x, bh = blockIdx.y, b = bh >> 4, h = bh & 15;
    __shared__ float Ps[32][64];             // [k][row]
    __shared__ float Vs[32][64];             // [k][col]
    const int tid = threadIdx.x, tx = tid & 15, ty = tid >> 4;

    const float* prow = sc + (size_t)bh * T * T + (size_t)(it * 64) * T;
    const size_t vbase = (size_t)b * T * D3 + 2 * D + h * DH;
    const int kmax = (it + 1) * 64;          // causal: P is zero beyond

    float acc[4][4] = {};
    for (int k0 = 0; k0 < kmax; k0 += 32) {
        #pragma unroll
        for (int i = 0; i < 2; i++) {        // P tile 64x32
            const int f = tid + i * 256;
            const int r = f >> 3, c4 = (f & 7) << 2;
            const float4 p = *(const float4*)(prow + (size_t)r * T + k0 + c4);
            Ps[c4 + 0][r] = p.x; Ps[c4 + 1][r] = p.y;
            Ps[c4 + 2][r] = p.z; Ps[c4 + 3][r] = p.w;
        }
        #pragma unroll
        for (int i = 0; i < 2; i++) {        // V tile 32x64
            const int f = tid + i * 256;
            const int r = f >> 4, c4 = (f & 15) << 2;
            *(float4*)&Vs[r][c4] =
                *(const float4*)(qkv + vbase + (size_t)(k0 + r) * D3 + c4);
        }
        __syncthreads();
        #pragma unroll
        for (int k = 0; k < 32; k++) {
            float a[4], bb[4];
            *(float4*)a  = *(const float4*)&Ps[k][ty * 4];
            *(float4*)bb = *(const float4*)&Vs[k][tx * 4];
            #pragma unroll
            for (int i = 0; i < 4; i++)
                #pragma unroll
                for (int j = 0; j < 4; j++)
                    acc[i][j] += a[i] * bb[j];
        }
        __syncthreads();
    }

    float* orow = o + ((size_t)b * T + it * 64) * D + h * DH;
    #pragma unroll
    for (int i = 0; i < 4; i++)
        #pragma unroll
        for (int j = 0; j < 4; j++)
            orow[(size_t)(ty * 4 + i) * D + tx * 4 + j] = acc[i][j];
}

// ---------------------------------------------------------------------------
// Launcher: embed -> 6x(ln1, qkv, attn, wout+res, ln2, ffn1+gelu, ffn2+res)
//           -> final ln into d_out. All plain launches; graph-capturable.
// ---------------------------------------------------------------------------
extern "C" void kernel_launch(void* const* d_in, const int* in_sizes, int n_in,
                              void* d_out, int out_size)
{
    const int*   ids   = (const int*)  d_in[0];
    const float* tok   = (const float*)d_in[1];
    const float* pos   = (const float*)d_in[2];
    const float* ln1_s = (const float*)d_in[3];
    const float* ln1_b = (const float*)d_in[4];
    const float* Wqkv  = (const float*)d_in[5];
    const float* Wout  = (const float*)d_in[6];
    const float* ln2_s = (const float*)d_in[7];
    const float* ln2_b = (const float*)d_in[8];
    const float* W1    = (const float*)d_in[9];
    const float* W2    = (const float*)d_in[10];
    const float* lnf_s = (const float*)d_in[11];
    const float* lnf_b = (const float*)d_in[12];
    float* out = (float*)d_out;

    float *x, *h, *qkv, *ffn, *sc;
    cudaGetSymbolAddress((void**)&x,   g_x);
    cudaGetSymbolAddress((void**)&h,   g_h);
    cudaGetSymbolAddress((void**)&qkv, g_qkv);
    cudaGetSymbolAddress((void**)&ffn, g_ffn);
    cudaGetSymbolAddress((void**)&sc,  g_sc);

    embed_kernel<<<MR, 256>>>(ids, tok, pos, x);

    for (int l = 0; l < Lx; l++) {
        const float* wqkv = Wqkv + (size_t)l * D * D3;
        const float* wout = Wout + (size_t)l * D * D;
        const float* w1   = W1   + (size_t)l * D * DFF;
        const float* w2   = W2   + (size_t)l * DFF * D;

        ln_kernel<<<MR, 256>>>(x, ln1_s + l * D, ln1_b + l * D, h);
        gemm_kernel<0><<<dim3(D3 / 128, MR / 128), 256>>>(
            h, wqkv, nullptr, qkv, MR, D3, D);

        scores_kernel<<<dim3(T / 64, T / 64, Bx * H), 256>>>(qkv, sc);
        softmax_kernel<<<Bx * H * T, 256>>>(sc);
        attnv_kernel<<<dim3(T / 64, Bx * H), 256>>>(sc, qkv, h);

        gemm_kernel<2><<<dim3(D / 128, MR / 128), 256>>>(
            h, wout, x, x, MR, D, D);           // x = x + h @ Wout

        ln_kernel<<<MR, 256>>>(x, ln2_s + l * D, ln2_b + l * D, h);
        gemm_kernel<1><<<dim3(DFF / 128, MR / 128), 256>>>(
            h, w1, nullptr, ffn, MR, DFF, D);   // ffn = gelu(h @ W1)
        gemm_kernel<2><<<dim3(D / 128, MR / 128), 256>>>(
            ffn, w2, x, x, MR, D, DFF);         // x = x + ffn @ W2
    }

    ln_kernel<<<MR, 256>>>(x, lnf_s, lnf_b, out);
}

// round 6
// speedup vs baseline: 1.7810x; 1.7810x over previous
#include <cuda_runtime.h>
#include <cuda_bf16.h>
#include <math_constants.h>
#include <cstdint>

// ---------------------------------------------------------------------------
// Constants
// ---------------------------------------------------------------------------
namespace {
constexpr int Bx  = 2;
constexpr int T   = 1024;
constexpr int D   = 1024;
constexpr int H   = 16;
constexpr int Lx  = 6;
constexpr int DH  = 64;
constexpr int DFF = 2048;
constexpr int MR  = Bx * T;     // 2048
constexpr int D3  = 3 * D;      // 3072

// GEMM smem: 2 stages x 4 arrays (Ah, Al, Bh, Bl) x 128 rows x 80B pitch
constexpr int PITCH_B   = 80;                  // 32 bf16 (64B) + 16B pad
constexpr int ARR_B     = 128 * PITCH_B;       // 10240
constexpr int STG_B     = 4 * ARR_B;           // 40960
constexpr int GEMM_SMEM = 2 * STG_B;           // 81920
}

// ---------------------------------------------------------------------------
// Scratch (device globals; allocation-free per harness rules)
// ---------------------------------------------------------------------------
__device__ float g_x  [MR * D];                        // residual stream
__device__ float g_qkv[MR * D3];
__device__ float g_sc [(size_t)Bx * H * T * T];        // 128 MB scores/probs
__device__ __align__(16) __nv_bfloat16 g_ah[MR * DFF];
__device__ __align__(16) __nv_bfloat16 g_al[MR * DFF];
__device__ __align__(16) __nv_bfloat16 g_bh[MR * DFF];
__device__ __align__(16) __nv_bfloat16 g_bl[MR * DFF];
// Transposed+split weights [N, K] bf16
__device__ __align__(16) __nv_bfloat16 g_wqkv_h[Lx * D3 * D];
__device__ __align__(16) __nv_bfloat16 g_wqkv_l[Lx * D3 * D];
__device__ __align__(16) __nv_bfloat16 g_wout_h[Lx * D * D];
__device__ __align__(16) __nv_bfloat16 g_wout_l[Lx * D * D];
__device__ __align__(16) __nv_bfloat16 g_w1_h  [Lx * DFF * D];
__device__ __align__(16) __nv_bfloat16 g_w1_l  [Lx * DFF * D];
__device__ __align__(16) __nv_bfloat16 g_w2_h  [Lx * D * DFF];
__device__ __align__(16) __nv_bfloat16 g_w2_l  [Lx * D * DFF];

// ---------------------------------------------------------------------------
// PTX helpers (all baseline sm_80+ instructions; no arch-specific features)
// ---------------------------------------------------------------------------
__device__ __forceinline__ uint32_t smem_u32(const void* p) {
    uint32_t a;
    asm("{ .reg .u64 t; cvta.to.shared.u64 t, %1; cvt.u32.u64 %0, t; }"
        : "=r"(a) : "l"(p));
    return a;
}
#define CP16(dst, src)                                                         \
    asm volatile("cp.async.cg.shared.global [%0], [%1], 16;"                   \
                 :: "r"(dst), "l"(src))
#define CP_COMMIT()  asm volatile("cp.async.commit_group;" ::: "memory")
#define CP_WAIT(n)   asm volatile("cp.async.wait_group %0;" :: "n"(n) : "memory")

#define LDSM4(r0, r1, r2, r3, addr)                                            \
    asm volatile("ldmatrix.sync.aligned.m8n8.x4.shared.b16 {%0,%1,%2,%3}, [%4];" \
                 : "=r"(r0), "=r"(r1), "=r"(r2), "=r"(r3) : "r"(addr))

#define MMA_BF16(c, a, b)                                                      \
    asm volatile("mma.sync.aligned.m16n8k16.row.col.f32.bf16.bf16.f32 "        \
                 "{%0,%1,%2,%3}, {%4,%5,%6,%7}, {%8,%9}, {%0,%1,%2,%3};"       \
                 : "+f"((c)[0]), "+f"((c)[1]), "+f"((c)[2]), "+f"((c)[3])      \
                 : "r"((a)[0]), "r"((a)[1]), "r"((a)[2]), "r"((a)[3]),         \
                   "r"((b)[0]), "r"((b)[1]))

__device__ __forceinline__ void split2(float v, __nv_bfloat16& h, __nv_bfloat16& l) {
    h = __float2bfloat16(v);
    l = __float2bfloat16(v - __bfloat162float(h));
}
__device__ __forceinline__ float gelu_exact(float v) {
    return 0.5f * v * (1.0f + erff(v * 0.70710678118654752f));
}

// ---------------------------------------------------------------------------
// Embedding
// ---------------------------------------------------------------------------
__global__ __launch_bounds__(256) void embed_kernel(
    const int* __restrict__ ids, const float* __restrict__ tok,
    const float* __restrict__ pos, float* __restrict__ x)
{
    const int row = blockIdx.x;
    const int t   = row & (T - 1);
    const int id  = ids[row];
    const float4* te = (const float4*)(tok + (size_t)id * D);
    const float4* pe = (const float4*)(pos + (size_t)t  * D);
    float4*       xr = (float4*)(x + (size_t)row * D);
    const int c = threadIdx.x;
    float4 a = te[c], b = pe[c];
    xr[c] = make_float4(a.x + b.x, a.y + b.y, a.z + b.z, a.w + b.w);
}

// ---------------------------------------------------------------------------
// LayerNorm variants
// ---------------------------------------------------------------------------
__device__ __forceinline__ void ln_stats(const float4 v, int tid,
                                         float& mean, float& rstd,
                                         float* r1, float* r2)
{
    float sum = v.x + v.y + v.z + v.w;
    float sq  = v.x * v.x + v.y * v.y + v.z * v.z + v.w * v.w;
    r1[tid] = sum; r2[tid] = sq;
    __syncthreads();
    #pragma unroll
    for (int st = 128; st > 0; st >>= 1) {
        if (tid < st) { r1[tid] += r1[tid + st]; r2[tid] += r2[tid + st]; }
        __syncthreads();
    }
    mean = r1[0] * (1.0f / D);
    const float var = r2[0] * (1.0f / D) - mean * mean;
    rstd = rsqrtf(var + 1e-5f);
}

__global__ __launch_bounds__(256) void ln_kernel(
    const float* __restrict__ x, const float* __restrict__ s,
    const float* __restrict__ b, float* __restrict__ out)
{
    const int row = blockIdx.x, tid = threadIdx.x;
    const float4 v = ((const float4*)(x + (size_t)row * D))[tid];
    __shared__ float r1[256], r2[256];
    float mean, rstd;
    ln_stats(v, tid, mean, rstd, r1, r2);
    const float4 sv = ((const float4*)s)[tid];
    const float4 bv = ((const float4*)b)[tid];
    float4 o;
    o.x = (v.x - mean) * rstd * sv.x + bv.x;
    o.y = (v.y - mean) * rstd * sv.y + bv.y;
    o.z = (v.z - mean) * rstd * sv.z + bv.z;
    o.w = (v.w - mean) * rstd * sv.w + bv.w;
    ((float4*)(out + (size_t)row * D))[tid] = o;
}

// LayerNorm that writes split bf16 hi/lo (feeds tensor-core GEMM)
__global__ __launch_bounds__(256) void ln_split_kernel(
    const float* __restrict__ x, const float* __restrict__ s,
    const float* __restrict__ b,
    __nv_bfloat16* __restrict__ ah, __nv_bfloat16* __restrict__ al)
{
    const int row = blockIdx.x, tid = threadIdx.x;
    const float4 v = ((const float4*)(x + (size_t)row * D))[tid];
    __shared__ float r1[256], r2[256];
    float mean, rstd;
    ln_stats(v, tid, mean, rstd, r1, r2);
    const float4 sv = ((const float4*)s)[tid];
    const float4 bv = ((const float4*)b)[tid];
    float o[4];
    o[0] = (v.x - mean) * rstd * sv.x + bv.x;
    o[1] = (v.y - mean) * rstd * sv.y + bv.y;
    o[2] = (v.z - mean) * rstd * sv.z + bv.z;
    o[3] = (v.w - mean) * rstd * sv.w + bv.w;
    const size_t base = (size_t)row * D + (tid << 2);
    __nv_bfloat162 h01, h23, l01, l23;
    split2(o[0], h01.x, l01.x); split2(o[1], h01.y, l01.y);
    split2(o[2], h23.x, l23.x); split2(o[3], h23.y, l23.y);
    *(__nv_bfloat162*)(ah + base)     = h01;
    *(__nv_bfloat162*)(ah + base + 2) = h23;
    *(__nv_bfloat162*)(al + base)     = l01;
    *(__nv_bfloat162*)(al + base + 2) = l23;
}

// ---------------------------------------------------------------------------
// Weight prep: W[K,N] fp32 -> hi/lo bf16 [N,K] (transpose + split)
// ---------------------------------------------------------------------------
__global__ __launch_bounds__(256) void tsplit_kernel(
    const float* __restrict__ W, __nv_bfloat16* __restrict__ oh,
    __nv_bfloat16* __restrict__ ol, int Kd, int Nd)
{
    __shared__ float s[32][33];
    const int n0 = blockIdx.x * 32, k0 = blockIdx.y * 32;
    const int tx = threadIdx.x & 31, ty = threadIdx.x >> 5;
    #pragma unroll
    for (int j = 0; j < 4; j++)
        s[ty + j * 8][tx] = W[(size_t)(k0 + ty + j * 8) * Nd + n0 + tx];
    __syncthreads();
    #pragma unroll
    for (int j = 0; j < 4; j++) {
        const float v = s[tx][ty + j * 8];
        __nv_bfloat16 h, l;
        split2(v, h, l);
        const size_t idx = (size_t)(n0 + ty + j * 8) * Kd + k0 + tx;
        oh[idx] = h; ol[idx] = l;
    }
}

// ---------------------------------------------------------------------------
// Warp-MMA GEMM: C[M,N] = A[M,K] * B[N,K]^T, 3-term bf16 split, fp32 accum.
// CTA tile 128x128, BK=32, 8 warps (4m x 2n), warp tile 32x64.
// cp.async double-buffered smem, ldmatrix fragments, mma.sync m16n8k16.
// EPI: 0 = fp32 store, 1 = exact GELU -> bf16 hi/lo, 2 = residual add fp32
// ---------------------------------------------------------------------------
template <int EPI>
__global__ __launch_bounds__(256) void gemm_mma(
    const __nv_bfloat16* __restrict__ Ah, const __nv_bfloat16* __restrict__ Al,
    const __nv_bfloat16* __restrict__ Bh, const __nv_bfloat16* __restrict__ Bl,
    const float* __restrict__ R, float* __restrict__ Cf,
    __nv_bfloat16* __restrict__ Ch, __nv_bfloat16* __restrict__ Cl,
    int Ndim, int Kdim)
{
    extern __shared__ char smem[];
    const uint32_t sbase = smem_u32(smem);
    const int tid = threadIdx.x, wid = tid >> 5, lane = tid & 31;
    const int row0 = blockIdx.y << 7, col0 = blockIdx.x << 7;
    const int wm = wid & 3;          // 0..3 -> 32-row slice
    const int wn = wid >> 2;         // 0..1 -> 64-col slice

    const int nC = Kdim >> 5;        // BK = 32

    float acc[2][8][4];
    #pragma unroll
    for (int a = 0; a < 2; a++)
        #pragma unroll
        for (int b = 0; b < 8; b++)
            #pragma unroll
            for (int c = 0; c < 4; c++) acc[a][b][c] = 0.f;

    // ---- issue chunk c loads into stage (c&1) ----
    auto issue = [&](int c) {
        const int s = c & 1;
        const int k0 = c << 5;
        const uint32_t sb = sbase + s * STG_B;
        #pragma unroll
        for (int i = 0; i < 8; i++) {
            const int rem = tid + ((i & 1) << 8);
            const int row = rem >> 2, c16 = rem & 3;
            const uint32_t dst = sb + (i >> 1) * ARR_B + row * PITCH_B + c16 * 16;
            const __nv_bfloat16* src;
            if ((i >> 1) == 0)      src = Ah + (size_t)(row0 + row) * Kdim + k0 + c16 * 8;
            else if ((i >> 1) == 1) src = Al + (size_t)(row0 + row) * Kdim + k0 + c16 * 8;
            else if ((i >> 1) == 2) src = Bh + (size_t)(col0 + row) * Kdim + k0 + c16 * 8;
            else                    src = Bl + (size_t)(col0 + row) * Kdim + k0 + c16 * 8;
            CP16(dst, src);
        }
        CP_COMMIT();
    };

    issue(0);

    for (int c = 0; c < nC; ++c) {
        const int s = c & 1;
        if (c + 1 < nC) { issue(c + 1); CP_WAIT(1); }
        else            { CP_WAIT(0); }
        __syncthreads();

        const uint32_t sa_h = sbase + s * STG_B;
        const uint32_t sa_l = sa_h + ARR_B;
        const uint32_t sb_h = sa_h + 2 * ARR_B;
        const uint32_t sb_l = sa_h + 3 * ARR_B;

        #pragma unroll
        for (int ks = 0; ks < 2; ks++) {
            uint32_t a_h[2][4], a_l[2][4], b_h[8][2], b_l[8][2];
            const uint32_t kb = ks * 32;          // 16 bf16 = 32 bytes
            #pragma unroll
            for (int mi = 0; mi < 2; mi++) {
                const int mrow = wm * 32 + mi * 16 + (lane & 15);
                const uint32_t off = mrow * PITCH_B + kb + ((lane >> 4) << 4);
                LDSM4(a_h[mi][0], a_h[mi][1], a_h[mi][2], a_h[mi][3], sa_h + off);
                LDSM4(a_l[mi][0], a_l[mi][1], a_l[mi][2], a_l[mi][3], sa_l + off);
            }
            #pragma unroll
            for (int nb = 0; nb < 4; nb++) {
                const int nrow = wn * 64 + nb * 16 + (((lane >> 4) & 1) << 3) + (lane & 7);
                const uint32_t off = nrow * PITCH_B + kb + (((lane >> 3) & 1) << 4);
                LDSM4(b_h[2 * nb][0], b_h[2 * nb][1],
                      b_h[2 * nb + 1][0], b_h[2 * nb + 1][1], sb_h + off);
                LDSM4(b_l[2 * nb][0], b_l[2 * nb][1],
                      b_l[2 * nb + 1][0], b_l[2 * nb + 1][1], sb_l + off);
            }
            #pragma unroll
            for (int mi = 0; mi < 2; mi++)
                #pragma unroll
                for (int ni = 0; ni < 8; ni++) {
                    MMA_BF16(acc[mi][ni], a_h[mi], b_h[ni]);
                    MMA_BF16(acc[mi][ni], a_h[mi], b_l[ni]);
                    MMA_BF16(acc[mi][ni], a_l[mi], b_h[ni]);
                }
        }
        __syncthreads();
    }

    // ---- epilogue ----
    #pragma unroll
    for (int mi = 0; mi < 2; mi++) {
        #pragma unroll
        for (int ni = 0; ni < 8; ni++) {
            const int r0 = row0 + wm * 32 + mi * 16 + (lane >> 2);
            const int r1 = r0 + 8;
            const int cc = col0 + wn * 64 + ni * 8 + ((lane & 3) << 1);
            const float* a = acc[mi][ni];
            if (EPI == 0) {
                *(float2*)(Cf + (size_t)r0 * Ndim + cc) = make_float2(a[0], a[1]);
                *(float2*)(Cf + (size_t)r1 * Ndim + cc) = make_float2(a[2], a[3]);
            } else if (EPI == 2) {
                const float2 q0 = *(const float2*)(R + (size_t)r0 * Ndim + cc);
                const float2 q1 = *(const float2*)(R + (size_t)r1 * Ndim + cc);
                *(float2*)(Cf + (size_t)r0 * Ndim + cc) = make_float2(a[0] + q0.x, a[1] + q0.y);
                *(float2*)(Cf + (size_t)r1 * Ndim + cc) = make_float2(a[2] + q1.x, a[3] + q1.y);
            } else {
                const float v0 = gelu_exact(a[0]), v1 = gelu_exact(a[1]);
                const float v2 = gelu_exact(a[2]), v3 = gelu_exact(a[3]);
                __nv_bfloat162 h0, l0, h1, l1;
                split2(v0, h0.x, l0.x); split2(v1, h0.y, l0.y);
                split2(v2, h1.x, l1.x); split2(v3, h1.y, l1.y);
                *(__nv_bfloat162*)(Ch + (size_t)r0 * Ndim + cc) = h0;
                *(__nv_bfloat162*)(Cl + (size_t)r0 * Ndim + cc) = l0;
                *(__nv_bfloat162*)(Ch + (size_t)r1 * Ndim + cc) = h1;
                *(__nv_bfloat162*)(Cl + (size_t)r1 * Ndim + cc) = l1;
            }
        }
    }
}

// ---------------------------------------------------------------------------
// Attention (SIMT fp32 this round; tensorization queued)
// ---------------------------------------------------------------------------
__global__ __launch_bounds__(256) void scores_kernel(
    const float* __restrict__ qkv, float* __restrict__ sc)
{
    const int jt = blockIdx.x, it = blockIdx.y;
    if (jt > it) return;
    const int bh = blockIdx.z, b = bh >> 4, h = bh & 15;

    __shared__ float Qs[64][64];
    __shared__ float Ks[64][64];
    const int tid = threadIdx.x;

    const size_t qbase = ((size_t)b * T + it * 64) * D3 + h * DH;
    const size_t kbase = ((size_t)b * T + jt * 64) * D3 + D + h * DH;

    #pragma unroll
    for (int i = 0; i < 4; i++) {
        const int f = tid + i * 256;
        const int r = f >> 4, c4 = (f & 15) << 2;
        const float4 q = *(const float4*)(qkv + qbase + (size_t)r * D3 + c4);
        Qs[c4 + 0][r] = q.x; Qs[c4 + 1][r] = q.y;
        Qs[c4 + 2][r] = q.z; Qs[c4 + 3][r] = q.w;
        const float4 kk = *(const float4*)(qkv + kbase + (size_t)r * D3 + c4);
        Ks[c4 + 0][r] = kk.x; Ks[c4 + 1][r] = kk.y;
        Ks[c4 + 2][r] = kk.z; Ks[c4 + 3][r] = kk.w;
    }
    __syncthreads();

    const int tx = tid & 15, ty = tid >> 4;
    float acc[4][4] = {};
    #pragma unroll
    for (int k = 0; k < 64; k++) {
        float a[4], bb[4];
        *(float4*)a  = *(const float4*)&Qs[k][ty * 4];
        *(float4*)bb = *(const float4*)&Ks[k][tx * 4];
        #pragma unroll
        for (int i = 0; i < 4; i++)
            #pragma unroll
            for (int j = 0; j < 4; j++)
                acc[i][j] += a[i] * bb[j];
    }

    float* out = sc + (size_t)bh * T * T + (size_t)(it * 64) * T + jt * 64;
    #pragma unroll
    for (int i = 0; i < 4; i++)
        #pragma unroll
        for (int j = 0; j < 4; j++)
            out[(size_t)(ty * 4 + i) * T + tx * 4 + j] = acc[i][j] * 0.125f;
}

__global__ __launch_bounds__(256) void softmax_kernel(float* __restrict__ sc)
{
    const int g = blockIdx.x;
    const int i = g & (T - 1);
    const int n = i + 1;
    float* row = sc + (size_t)g * T;
    const int tid = threadIdx.x;
    __shared__ float red[256];

    float m = -CUDART_INF_F;
    for (int j = tid; j < n; j += 256) m = fmaxf(m, row[j]);
    red[tid] = m; __syncthreads();
    #pragma unroll
    for (int st = 128; st > 0; st >>= 1) {
        if (tid < st) red[tid] = fmaxf(red[tid], red[tid + st]);
        __syncthreads();
    }
    m = red[0];
    __syncthreads();

    float sum = 0.f;
    for (int j = tid; j < n; j += 256) {
        const float e = expf(row[j] - m);
        row[j] = e;
        sum += e;
    }
    red[tid] = sum; __syncthreads();
    #pragma unroll
    for (int st = 128; st > 0; st >>= 1) {
        if (tid < st) red[tid] += red[tid + st];
        __syncthreads();
    }
    const float inv = 1.0f / red[0];

    for (int j = tid; j < T; j += 256)
        row[j] = (j < n) ? row[j] * inv : 0.0f;
}

// O = P * V, output written as split bf16 hi/lo (feeds Wout GEMM)
__global__ __launch_bounds__(256) void attnv_kernel(
    const float* __restrict__ sc, const float* __restrict__ qkv,
    __nv_bfloat16* __restrict__ oh, __nv_bfloat16* __restrict__ ol)
{
    const int it = blockIdx.x, bh = blockIdx.y, b = bh >> 4, h = bh & 15;
    __shared__ float Ps[32][64];
    __shared__ float Vs[32][64];
    const int tid = threadIdx.x, tx = tid & 15, ty = tid >> 4;

    const float* prow = sc + (size_t)bh * T * T + (size_t)(it * 64) * T;
    const size_t vbase = (size_t)b * T * D3 + 2 * D + h * DH;
    const int kmax = (it + 1) * 64;

    float acc[4][4] = {};
    for (int k0 = 0; k0 < kmax; k0 += 32) {
        #pragma unroll
        for (int i = 0; i < 2; i++) {
            const int f = tid + i * 256;
            const int r = f >> 3, c4 = (f & 7) << 2;
            const float4 p = *(const float4*)(prow + (size_t)r * T + k0 + c4);
            Ps[c4 + 0][r] = p.x; Ps[c4 + 1][r] = p.y;
            Ps[c4 + 2][r] = p.z; Ps[c4 + 3][r] = p.w;
        }
        #pragma unroll
        for (int i = 0; i < 2; i++) {
            const int f = tid + i * 256;
            const int r = f >> 4, c4 = (f & 15) << 2;
            *(float4*)&Vs[r][c4] =
                *(const float4*)(qkv + vbase + (size_t)(k0 + r) * D3 + c4);
        }
        __syncthreads();
        #pragma unroll
        for (int k = 0; k < 32; k++) {
            float a[4], bb[4];
            *(float4*)a  = *(const float4*)&Ps[k][ty * 4];
            *(float4*)bb = *(const float4*)&Vs[k][tx * 4];
            #pragma unroll
            for (int i = 0; i < 4; i++)
                #pragma unroll
                for (int j = 0; j < 4; j++)
                    acc[i][j] += a[i] * bb[j];
        }
        __syncthreads();
    }

    const size_t obase = ((size_t)b * T + it * 64) * D + h * DH;
    #pragma unroll
    for (int i = 0; i < 4; i++)
        #pragma unroll
        for (int j = 0; j < 4; j++) {
            const size_t idx = obase + (size_t)(ty * 4 + i) * D + tx * 4 + j;
            __nv_bfloat16 hv, lv;
            split2(acc[i][j], hv, lv);
            oh[idx] = hv; ol[idx] = lv;
        }
}

// ---------------------------------------------------------------------------
// Launcher
// ---------------------------------------------------------------------------
extern "C" void kernel_launch(void* const* d_in, const int* in_sizes, int n_in,
                              void* d_out, int out_size)
{
    const int*   ids   = (const int*)  d_in[0];
    const float* tok   = (const float*)d_in[1];
    const float* pos   = (const float*)d_in[2];
    const float* ln1_s = (const float*)d_in[3];
    const float* ln1_b = (const float*)d_in[4];
    const float* Wqkv  = (const float*)d_in[5];
    const float* Wout  = (const float*)d_in[6];
    const float* ln2_s = (const float*)d_in[7];
    const float* ln2_b = (const float*)d_in[8];
    const float* W1    = (const float*)d_in[9];
    const float* W2    = (const float*)d_in[10];
    const float* lnf_s = (const float*)d_in[11];
    const float* lnf_b = (const float*)d_in[12];
    float* out = (float*)d_out;

    float *x, *qkv, *sc;
    __nv_bfloat16 *ah, *al, *bh, *bl;
    __nv_bfloat16 *wqh, *wql, *woh, *wol, *w1h, *w1l, *w2h, *w2l;
    cudaGetSymbolAddress((void**)&x,   g_x);
    cudaGetSymbolAddress((void**)&qkv, g_qkv);
    cudaGetSymbolAddress((void**)&sc,  g_sc);
    cudaGetSymbolAddress((void**)&ah,  g_ah);
    cudaGetSymbolAddress((void**)&al,  g_al);
    cudaGetSymbolAddress((void**)&bh,  g_bh);
    cudaGetSymbolAddress((void**)&bl,  g_bl);
    cudaGetSymbolAddress((void**)&wqh, g_wqkv_h);
    cudaGetSymbolAddress((void**)&wql, g_wqkv_l);
    cudaGetSymbolAddress((void**)&woh, g_wout_h);
    cudaGetSymbolAddress((void**)&wol, g_wout_l);
    cudaGetSymbolAddress((void**)&w1h, g_w1_h);
    cudaGetSymbolAddress((void**)&w1l, g_w1_l);
    cudaGetSymbolAddress((void**)&w2h, g_w2_h);
    cudaGetSymbolAddress((void**)&w2l, g_w2_l);

    cudaFuncSetAttribute(gemm_mma<0>, cudaFuncAttributeMaxDynamicSharedMemorySize, GEMM_SMEM);
    cudaFuncSetAttribute(gemm_mma<1>, cudaFuncAttributeMaxDynamicSharedMemorySize, GEMM_SMEM);
    cudaFuncSetAttribute(gemm_mma<2>, cudaFuncAttributeMaxDynamicSharedMemorySize, GEMM_SMEM);

    // Weight prep (transpose + bf16 split), every replay (deterministic)
    for (int l = 0; l < Lx; l++) {
        tsplit_kernel<<<dim3(D3 / 32, D / 32),  256>>>(Wqkv + (size_t)l * D * D3,
            wqh + (size_t)l * D3 * D,  wql + (size_t)l * D3 * D,  D,  D3);
        tsplit_kernel<<<dim3(D / 32, D / 32),   256>>>(Wout + (size_t)l * D * D,
            woh + (size_t)l * D * D,   wol + (size_t)l * D * D,   D,  D);
        tsplit_kernel<<<dim3(DFF / 32, D / 32), 256>>>(W1 + (size_t)l * D * DFF,
            w1h + (size_t)l * DFF * D, w1l + (size_t)l * DFF * D, D,  DFF);
        tsplit_kernel<<<dim3(D / 32, DFF / 32), 256>>>(W2 + (size_t)l * DFF * D,
            w2h + (size_t)l * D * DFF, w2l + (size_t)l * D * DFF, DFF, D);
    }

    embed_kernel<<<MR, 256>>>(ids, tok, pos, x);

    for (int l = 0; l < Lx; l++) {
        ln_split_kernel<<<MR, 256>>>(x, ln1_s + l * D, ln1_b + l * D, ah, al);
        gemm_mma<0><<<dim3(D3 / 128, MR / 128), 256, GEMM_SMEM>>>(
            ah, al, wqh + (size_t)l * D3 * D, wql + (size_t)l * D3 * D,
            nullptr, qkv, nullptr, nullptr, D3, D);

        scores_kernel<<<dim3(T / 64, T / 64, Bx * H), 256>>>(qkv, sc);
        softmax_kernel<<<Bx * H * T, 256>>>(sc);
        attnv_kernel<<<dim3(T / 64, Bx * H), 256>>>(sc, qkv, ah, al);

        gemm_mma<2><<<dim3(D / 128, MR / 128), 256, GEMM_SMEM>>>(
            ah, al, woh + (size_t)l * D * D, wol + (size_t)l * D * D,
            x, x, nullptr, nullptr, D, D);

        ln_split_kernel<<<MR, 256>>>(x, ln2_s + l * D, ln2_b + l * D, ah, al);
        gemm_mma<1><<<dim3(DFF / 128, MR / 128), 256, GEMM_SMEM>>>(
            ah, al, w1h + (size_t)l * DFF * D, w1l + (size_t)l * DFF * D,
            nullptr, nullptr, bh, bl, DFF, D);
        gemm_mma<2><<<dim3(D / 128, MR / 128), 256, GEMM_SMEM>>>(
            bh, bl, w2h + (size_t)l * D * DFF, w2l + (size_t)l * D * DFF,
            x, x, nullptr, nullptr, D, DFF);
    }

    ln_kernel<<<MR, 256>>>(x, lnf_s, lnf_b, out);
}

// round 7
// speedup vs baseline: 2.3086x; 1.2962x over previous
#include <cuda_runtime.h>
#include <cuda_bf16.h>
#include <math_constants.h>
#include <cstdint>

// ---------------------------------------------------------------------------
// Constants
// ---------------------------------------------------------------------------
namespace {
constexpr int Bx  = 2;
constexpr int T   = 1024;
constexpr int D   = 1024;
constexpr int H   = 16;
constexpr int Lx  = 6;
constexpr int DH  = 64;
constexpr int DFF = 2048;
constexpr int MR  = Bx * T;     // 2048
constexpr int D3  = 3 * D;      // 3072

// Big GEMM smem: 2 stages x 4 arrays x 128 rows x 80B pitch
constexpr int PITCH_B   = 80;
constexpr int ARR_B     = 128 * PITCH_B;       // 10240
constexpr int STG_B     = 4 * ARR_B;           // 40960
constexpr int GEMM_SMEM = 2 * STG_B;           // 81920

// Attention tiles: 64x64 bf16, 144B pitch (64*2=128B + 16 pad)
constexpr int APITCH    = 144;
constexpr int AARR      = 64 * APITCH;         // 9216
constexpr int SC_SMEM   = 4 * AARR;            // 36864 (static, 1 stage)
constexpr int AV_SMEM   = 2 * 4 * AARR;        // 73728 (dynamic, 2 stages)
}

// ---------------------------------------------------------------------------
// Scratch (device globals; allocation-free per harness rules)
// ---------------------------------------------------------------------------
__device__ float g_x  [MR * D];                        // residual stream
__device__ float g_sc [(size_t)Bx * H * T * T];        // fp32 scores
__device__ __align__(16) __nv_bfloat16 g_qh[MR * D3];  // qkv hi
__device__ __align__(16) __nv_bfloat16 g_ql[MR * D3];  // qkv lo
__device__ __align__(16) __nv_bfloat16 g_ph[(size_t)Bx * H * T * T]; // probs hi
__device__ __align__(16) __nv_bfloat16 g_pl[(size_t)Bx * H * T * T]; // probs lo
__device__ __align__(16) __nv_bfloat16 g_ah[MR * DFF];
__device__ __align__(16) __nv_bfloat16 g_al[MR * DFF];
__device__ __align__(16) __nv_bfloat16 g_bh[MR * DFF];
__device__ __align__(16) __nv_bfloat16 g_bl[MR * DFF];
// Transposed+split weights [N, K] bf16
__device__ __align__(16) __nv_bfloat16 g_wqkv_h[Lx * D3 * D];
__device__ __align__(16) __nv_bfloat16 g_wqkv_l[Lx * D3 * D];
__device__ __align__(16) __nv_bfloat16 g_wout_h[Lx * D * D];
__device__ __align__(16) __nv_bfloat16 g_wout_l[Lx * D * D];
__device__ __align__(16) __nv_bfloat16 g_w1_h  [Lx * DFF * D];
__device__ __align__(16) __nv_bfloat16 g_w1_l  [Lx * DFF * D];
__device__ __align__(16) __nv_bfloat16 g_w2_h  [Lx * D * DFF];
__device__ __align__(16) __nv_bfloat16 g_w2_l  [Lx * D * DFF];

// ---------------------------------------------------------------------------
// PTX helpers (baseline sm_80+)
// ---------------------------------------------------------------------------
__device__ __forceinline__ uint32_t smem_u32(const void* p) {
    uint32_t a;
    asm("{ .reg .u64 t; cvta.to.shared.u64 t, %1; cvt.u32.u64 %0, t; }"
        : "=r"(a) : "l"(p));
    return a;
}
#define CP16(dst, src)                                                         \
    asm volatile("cp.async.cg.shared.global [%0], [%1], 16;"                   \
                 :: "r"(dst), "l"(src))
#define CP_COMMIT()  asm volatile("cp.async.commit_group;" ::: "memory")
#define CP_WAIT(n)   asm volatile("cp.async.wait_group %0;" :: "n"(n) : "memory")

#define LDSM4(r0, r1, r2, r3, addr)                                            \
    asm volatile("ldmatrix.sync.aligned.m8n8.x4.shared.b16 {%0,%1,%2,%3}, [%4];" \
                 : "=r"(r0), "=r"(r1), "=r"(r2), "=r"(r3) : "r"(addr))
#define LDSM4T(r0, r1, r2, r3, addr)                                           \
    asm volatile("ldmatrix.sync.aligned.m8n8.x4.trans.shared.b16 {%0,%1,%2,%3}, [%4];" \
                 : "=r"(r0), "=r"(r1), "=r"(r2), "=r"(r3) : "r"(addr))

#define MMA_BF16(c, a, b)                                                      \
    asm volatile("mma.sync.aligned.m16n8k16.row.col.f32.bf16.bf16.f32 "        \
                 "{%0,%1,%2,%3}, {%4,%5,%6,%7}, {%8,%9}, {%0,%1,%2,%3};"       \
                 : "+f"((c)[0]), "+f"((c)[1]), "+f"((c)[2]), "+f"((c)[3])      \
                 : "r"((a)[0]), "r"((a)[1]), "r"((a)[2]), "r"((a)[3]),         \
                   "r"((b)[0]), "r"((b)[1]))

__device__ __forceinline__ void split2(float v, __nv_bfloat16& h, __nv_bfloat16& l) {
    h = __float2bfloat16(v);
    l = __float2bfloat16(v - __bfloat162float(h));
}
__device__ __forceinline__ float gelu_exact(float v) {
    return 0.5f * v * (1.0f + erff(v * 0.70710678118654752f));
}

// ---------------------------------------------------------------------------
// Embedding
// ---------------------------------------------------------------------------
__global__ __launch_bounds__(256) void embed_kernel(
    const int* __restrict__ ids, const float* __restrict__ tok,
    const float* __restrict__ pos, float* __restrict__ x)
{
    const int row = blockIdx.x;
    const int t   = row & (T - 1);
    const int id  = ids[row];
    const float4* te = (const float4*)(tok + (size_t)id * D);
    const float4* pe = (const float4*)(pos + (size_t)t  * D);
    float4*       xr = (float4*)(x + (size_t)row * D);
    const int c = threadIdx.x;
    float4 a = te[c], b = pe[c];
    xr[c] = make_float4(a.x + b.x, a.y + b.y, a.z + b.z, a.w + b.w);
}

// ---------------------------------------------------------------------------
// LayerNorm
// ---------------------------------------------------------------------------
__device__ __forceinline__ void ln_stats(const float4 v, int tid,
                                         float& mean, float& rstd,
                                         float* r1, float* r2)
{
    float sum = v.x + v.y + v.z + v.w;
    float sq  = v.x * v.x + v.y * v.y + v.z * v.z + v.w * v.w;
    r1[tid] = sum; r2[tid] = sq;
    __syncthreads();
    #pragma unroll
    for (int st = 128; st > 0; st >>= 1) {
        if (tid < st) { r1[tid] += r1[tid + st]; r2[tid] += r2[tid + st]; }
        __syncthreads();
    }
    mean = r1[0] * (1.0f / D);
    const float var = r2[0] * (1.0f / D) - mean * mean;
    rstd = rsqrtf(var + 1e-5f);
}

__global__ __launch_bounds__(256) void ln_kernel(
    const float* __restrict__ x, const float* __restrict__ s,
    const float* __restrict__ b, float* __restrict__ out)
{
    const int row = blockIdx.x, tid = threadIdx.x;
    const float4 v = ((const float4*)(x + (size_t)row * D))[tid];
    __shared__ float r1[256], r2[256];
    float mean, rstd;
    ln_stats(v, tid, mean, rstd, r1, r2);
    const float4 sv = ((const float4*)s)[tid];
    const float4 bv = ((const float4*)b)[tid];
    float4 o;
    o.x = (v.x - mean) * rstd * sv.x + bv.x;
    o.y = (v.y - mean) * rstd * sv.y + bv.y;
    o.z = (v.z - mean) * rstd * sv.z + bv.z;
    o.w = (v.w - mean) * rstd * sv.w + bv.w;
    ((float4*)(out + (size_t)row * D))[tid] = o;
}

__global__ __launch_bounds__(256) void ln_split_kernel(
    const float* __restrict__ x, const float* __restrict__ s,
    const float* __restrict__ b,
    __nv_bfloat16* __restrict__ ah, __nv_bfloat16* __restrict__ al)
{
    const int row = blockIdx.x, tid = threadIdx.x;
    const float4 v = ((const float4*)(x + (size_t)row * D))[tid];
    __shared__ float r1[256], r2[256];
    float mean, rstd;
    ln_stats(v, tid, mean, rstd, r1, r2);
    const float4 sv = ((const float4*)s)[tid];
    const float4 bv = ((const float4*)b)[tid];
    float o[4];
    o[0] = (v.x - mean) * rstd * sv.x + bv.x;
    o[1] = (v.y - mean) * rstd * sv.y + bv.y;
    o[2] = (v.z - mean) * rstd * sv.z + bv.z;
    o[3] = (v.w - mean) * rstd * sv.w + bv.w;
    const size_t base = (size_t)row * D + (tid << 2);
    __nv_bfloat162 h01, h23, l01, l23;
    split2(o[0], h01.x, l01.x); split2(o[1], h01.y, l01.y);
    split2(o[2], h23.x, l23.x); split2(o[3], h23.y, l23.y);
    *(__nv_bfloat162*)(ah + base)     = h01;
    *(__nv_bfloat162*)(ah + base + 2) = h23;
    *(__nv_bfloat162*)(al + base)     = l01;
    *(__nv_bfloat162*)(al + base + 2) = l23;
}

// ---------------------------------------------------------------------------
// Weight prep
// ---------------------------------------------------------------------------
__global__ __launch_bounds__(256) void tsplit_kernel(
    const float* __restrict__ W, __nv_bfloat16* __restrict__ oh,
    __nv_bfloat16* __restrict__ ol, int Kd, int Nd)
{
    __shared__ float s[32][33];
    const int n0 = blockIdx.x * 32, k0 = blockIdx.y * 32;
    const int tx = threadIdx.x & 31, ty = threadIdx.x >> 5;
    #pragma unroll
    for (int j = 0; j < 4; j++)
        s[ty + j * 8][tx] = W[(size_t)(k0 + ty + j * 8) * Nd + n0 + tx];
    __syncthreads();
    #pragma unroll
    for (int j = 0; j < 4; j++) {
        const float v = s[tx][ty + j * 8];
        __nv_bfloat16 h, l;
        split2(v, h, l);
        const size_t idx = (size_t)(n0 + ty + j * 8) * Kd + k0 + tx;
        oh[idx] = h; ol[idx] = l;
    }
}

// ---------------------------------------------------------------------------
// Warp-MMA GEMM (validated R6). EPI: 0 fp32, 1 GELU->split, 2 residual,
// 3 plain split bf16 store.
// ---------------------------------------------------------------------------
template <int EPI>
__global__ __launch_bounds__(256) void gemm_mma(
    const __nv_bfloat16* __restrict__ Ah, const __nv_bfloat16* __restrict__ Al,
    const __nv_bfloat16* __restrict__ Bh, const __nv_bfloat16* __restrict__ Bl,
    const float* __restrict__ R, float* __restrict__ Cf,
    __nv_bfloat16* __restrict__ Ch, __nv_bfloat16* __restrict__ Cl,
    int Ndim, int Kdim)
{
    extern __shared__ char smem[];
    const uint32_t sbase = smem_u32(smem);
    const int tid = threadIdx.x, wid = tid >> 5, lane = tid & 31;
    const int row0 = blockIdx.y << 7, col0 = blockIdx.x << 7;
    const int wm = wid & 3, wn = wid >> 2;
    const int nC = Kdim >> 5;

    float acc[2][8][4];
    #pragma unroll
    for (int a = 0; a < 2; a++)
        #pragma unroll
        for (int b = 0; b < 8; b++)
            #pragma unroll
            for (int c = 0; c < 4; c++) acc[a][b][c] = 0.f;

    auto issue = [&](int c) {
        const int s = c & 1;
        const int k0 = c << 5;
        const uint32_t sb = sbase + s * STG_B;
        #pragma unroll
        for (int i = 0; i < 8; i++) {
            const int rem = tid + ((i & 1) << 8);
            const int row = rem >> 2, c16 = rem & 3;
            const uint32_t dst = sb + (i >> 1) * ARR_B + row * PITCH_B + c16 * 16;
            const __nv_bfloat16* src;
            if ((i >> 1) == 0)      src = Ah + (size_t)(row0 + row) * Kdim + k0 + c16 * 8;
            else if ((i >> 1) == 1) src = Al + (size_t)(row0 + row) * Kdim + k0 + c16 * 8;
            else if ((i >> 1) == 2) src = Bh + (size_t)(col0 + row) * Kdim + k0 + c16 * 8;
            else                    src = Bl + (size_t)(col0 + row) * Kdim + k0 + c16 * 8;
            CP16(dst, src);
        }
        CP_COMMIT();
    };

    issue(0);

    for (int c = 0; c < nC; ++c) {
        const int s = c & 1;
        if (c + 1 < nC) { issue(c + 1); CP_WAIT(1); }
        else            { CP_WAIT(0); }
        __syncthreads();

        const uint32_t sa_h = sbase + s * STG_B;
        const uint32_t sa_l = sa_h + ARR_B;
        const uint32_t sb_h = sa_h + 2 * ARR_B;
        const uint32_t sb_l = sa_h + 3 * ARR_B;

        #pragma unroll
        for (int ks = 0; ks < 2; ks++) {
            uint32_t a_h[2][4], a_l[2][4], b_h[8][2], b_l[8][2];
            const uint32_t kb = ks * 32;
            #pragma unroll
            for (int mi = 0; mi < 2; mi++) {
                const int mrow = wm * 32 + mi * 16 + (lane & 15);
                const uint32_t off = mrow * PITCH_B + kb + ((lane >> 4) << 4);
                LDSM4(a_h[mi][0], a_h[mi][1], a_h[mi][2], a_h[mi][3], sa_h + off);
                LDSM4(a_l[mi][0], a_l[mi][1], a_l[mi][2], a_l[mi][3], sa_l + off);
            }
            #pragma unroll
            for (int nb = 0; nb < 4; nb++) {
                const int nrow = wn * 64 + nb * 16 + (((lane >> 4) & 1) << 3) + (lane & 7);
                const uint32_t off = nrow * PITCH_B + kb + (((lane >> 3) & 1) << 4);
                LDSM4(b_h[2 * nb][0], b_h[2 * nb][1],
                      b_h[2 * nb + 1][0], b_h[2 * nb + 1][1], sb_h + off);
                LDSM4(b_l[2 * nb][0], b_l[2 * nb][1],
                      b_l[2 * nb + 1][0], b_l[2 * nb + 1][1], sb_l + off);
            }
            #pragma unroll
            for (int mi = 0; mi < 2; mi++)
                #pragma unroll
                for (int ni = 0; ni < 8; ni++) {
                    MMA_BF16(acc[mi][ni], a_h[mi], b_h[ni]);
                    MMA_BF16(acc[mi][ni], a_h[mi], b_l[ni]);
                    MMA_BF16(acc[mi][ni], a_l[mi], b_h[ni]);
                }
        }
        __syncthreads();
    }

    #pragma unroll
    for (int mi = 0; mi < 2; mi++) {
        #pragma unroll
        for (int ni = 0; ni < 8; ni++) {
            const int r0 = row0 + wm * 32 + mi * 16 + (lane >> 2);
            const int r1 = r0 + 8;
            const int cc = col0 + wn * 64 + ni * 8 + ((lane & 3) << 1);
            const float* a = acc[mi][ni];
            if (EPI == 0) {
                *(float2*)(Cf + (size_t)r0 * Ndim + cc) = make_float2(a[0], a[1]);
                *(float2*)(Cf + (size_t)r1 * Ndim + cc) = make_float2(a[2], a[3]);
            } else if (EPI == 2) {
                const float2 q0 = *(const float2*)(R + (size_t)r0 * Ndim + cc);
                const float2 q1 = *(const float2*)(R + (size_t)r1 * Ndim + cc);
                *(float2*)(Cf + (size_t)r0 * Ndim + cc) = make_float2(a[0] + q0.x, a[1] + q0.y);
                *(float2*)(Cf + (size_t)r1 * Ndim + cc) = make_float2(a[2] + q1.x, a[3] + q1.y);
            } else {
                float v0 = a[0], v1 = a[1], v2 = a[2], v3 = a[3];
                if (EPI == 1) { v0 = gelu_exact(v0); v1 = gelu_exact(v1);
                                v2 = gelu_exact(v2); v3 = gelu_exact(v3); }
                __nv_bfloat162 h0, l0, h1, l1;
                split2(v0, h0.x, l0.x); split2(v1, h0.y, l0.y);
                split2(v2, h1.x, l1.x); split2(v3, h1.y, l1.y);
                *(__nv_bfloat162*)(Ch + (size_t)r0 * Ndim + cc) = h0;
                *(__nv_bfloat162*)(Cl + (size_t)r0 * Ndim + cc) = l0;
                *(__nv_bfloat162*)(Ch + (size_t)r1 * Ndim + cc) = h1;
                *(__nv_bfloat162*)(Cl + (size_t)r1 * Ndim + cc) = l1;
            }
        }
    }
}

// ---------------------------------------------------------------------------
// Scores: S[bh,it*64+,jt*64+] = (Q.K^T)/8 via mma, 3-term split. 1 stage.
// ---------------------------------------------------------------------------
__global__ __launch_bounds__(256) void scores_mma(
    const __nv_bfloat16* __restrict__ qh, const __nv_bfloat16* __restrict__ ql,
    float* __restrict__ sc)
{
    const int jt = blockIdx.x, it = blockIdx.y;
    if (jt > it) return;
    const int bh = blockIdx.z, b = bh >> 4, h = bh & 15;
    const int tid = threadIdx.x, wid = tid >> 5, lane = tid & 31;
    const int wm = wid & 3, wn = wid >> 2;

    __shared__ __align__(16) char smem[SC_SMEM];
    const uint32_t sbase = smem_u32(smem);
    const uint32_t sQh = sbase, sQl = sbase + AARR;
    const uint32_t sKh = sbase + 2 * AARR, sKl = sbase + 3 * AARR;

    const size_t qbase = ((size_t)b * T + it * 64) * D3 + h * DH;
    const size_t kbase = ((size_t)b * T + jt * 64) * D3 + D + h * DH;

    #pragma unroll
    for (int i = 0; i < 8; i++) {
        const int rem = tid + ((i & 1) << 8);
        const int row = rem >> 3, c16 = rem & 7;
        const uint32_t off = row * APITCH + c16 * 16;
        const __nv_bfloat16* src;
        uint32_t dst;
        if ((i >> 1) == 0)      { src = qh + qbase + (size_t)row * D3 + c16 * 8; dst = sQh + off; }
        else if ((i >> 1) == 1) { src = ql + qbase + (size_t)row * D3 + c16 * 8; dst = sQl + off; }
        else if ((i >> 1) == 2) { src = qh + kbase + (size_t)row * D3 + c16 * 8; dst = sKh + off; }
        else                    { src = ql + kbase + (size_t)row * D3 + c16 * 8; dst = sKl + off; }
        CP16(dst, src);
    }
    CP_COMMIT();
    CP_WAIT(0);
    __syncthreads();

    float acc[4][4] = {};
    #pragma unroll
    for (int ks = 0; ks < 4; ks++) {
        const uint32_t kb = ks * 32;
        uint32_t a_h[4], a_l[4], b_h[4][2], b_l[4][2];
        const uint32_t aoff = (wm * 16 + (lane & 15)) * APITCH + kb + ((lane >> 4) << 4);
        LDSM4(a_h[0], a_h[1], a_h[2], a_h[3], sQh + aoff);
        LDSM4(a_l[0], a_l[1], a_l[2], a_l[3], sQl + aoff);
        #pragma unroll
        for (int nb = 0; nb < 2; nb++) {
            const int nrow = wn * 32 + nb * 16 + (((lane >> 4) & 1) << 3) + (lane & 7);
            const uint32_t off = nrow * APITCH + kb + (((lane >> 3) & 1) << 4);
            LDSM4(b_h[2 * nb][0], b_h[2 * nb][1],
                  b_h[2 * nb + 1][0], b_h[2 * nb + 1][1], sKh + off);
            LDSM4(b_l[2 * nb][0], b_l[2 * nb][1],
                  b_l[2 * nb + 1][0], b_l[2 * nb + 1][1], sKl + off);
        }
        #pragma unroll
        for (int ni = 0; ni < 4; ni++) {
            MMA_BF16(acc[ni], a_h, b_h[ni]);
            MMA_BF16(acc[ni], a_h, b_l[ni]);
            MMA_BF16(acc[ni], a_l, b_h[ni]);
        }
    }

    float* out = sc + (size_t)bh * T * T;
    #pragma unroll
    for (int ni = 0; ni < 4; ni++) {
        const int r0 = it * 64 + wm * 16 + (lane >> 2);
        const int cc = jt * 64 + wn * 32 + ni * 8 + ((lane & 3) << 1);
        *(float2*)(out + (size_t)r0 * T + cc) =
            make_float2(acc[ni][0] * 0.125f, acc[ni][1] * 0.125f);
        *(float2*)(out + (size_t)(r0 + 8) * T + cc) =
            make_float2(acc[ni][2] * 0.125f, acc[ni][3] * 0.125f);
    }
}

// ---------------------------------------------------------------------------
// Causal softmax: fp32 scores -> split bf16 probs, zero-filled to tile edge.
// ---------------------------------------------------------------------------
__global__ __launch_bounds__(256) void softmax_kernel(
    const float* __restrict__ sc,
    __nv_bfloat16* __restrict__ ph, __nv_bfloat16* __restrict__ pl)
{
    const int g = blockIdx.x;
    const int i = g & (T - 1);
    const int n = i + 1;
    const int nn = (i & ~63) + 64;
    const float* row = sc + (size_t)g * T;
    __nv_bfloat16* rh = ph + (size_t)g * T;
    __nv_bfloat16* rl = pl + (size_t)g * T;
    const int tid = threadIdx.x;
    __shared__ float red[256];

    float m = -CUDART_INF_F;
    for (int j = tid; j < n; j += 256) m = fmaxf(m, row[j]);
    red[tid] = m; __syncthreads();
    #pragma unroll
    for (int st = 128; st > 0; st >>= 1) {
        if (tid < st) red[tid] = fmaxf(red[tid], red[tid + st]);
        __syncthreads();
    }
    m = red[0];
    __syncthreads();

    float sum = 0.f;
    for (int j = tid; j < n; j += 256) sum += expf(row[j] - m);
    red[tid] = sum; __syncthreads();
    #pragma unroll
    for (int st = 128; st > 0; st >>= 1) {
        if (tid < st) red[tid] += red[tid + st];
        __syncthreads();
    }
    const float inv = 1.0f / red[0];

    for (int j = tid; j < nn; j += 256) {
        float p = (j < n) ? expf(row[j] - m) * inv : 0.0f;
        __nv_bfloat16 hv, lv;
        split2(p, hv, lv);
        rh[j] = hv; rl[j] = lv;
    }
}

// ---------------------------------------------------------------------------
// O = P @ V via mma (A=P non-trans; B=V via ldmatrix.trans), 3-term split.
// Block: (it, bh). Double-buffered over jt tiles.
// ---------------------------------------------------------------------------
__global__ __launch_bounds__(256) void attnv_mma(
    const __nv_bfloat16* __restrict__ ph, const __nv_bfloat16* __restrict__ pl,
    const __nv_bfloat16* __restrict__ qh, const __nv_bfloat16* __restrict__ ql,
    __nv_bfloat16* __restrict__ oh, __nv_bfloat16* __restrict__ ol)
{
    extern __shared__ char smem[];
    const uint32_t sbase = smem_u32(smem);
    const int it = blockIdx.x, bh = blockIdx.y, b = bh >> 4, h = bh & 15;
    const int tid = threadIdx.x, wid = tid >> 5, lane = tid & 31;
    const int wm = wid & 3, wn = wid >> 2;

    const size_t pbase = (size_t)bh * T * T + (size_t)(it * 64) * T;
    const size_t vbase = (size_t)b * T * D3 + 2 * D + h * DH;
    const int nT = it + 1;

    float acc[4][4] = {};

    auto issue = [&](int jt) {
        const int s = jt & 1;
        const uint32_t sb = sbase + s * (4 * AARR);
        #pragma unroll
        for (int i = 0; i < 8; i++) {
            const int rem = tid + ((i & 1) << 8);
            const int row = rem >> 3, c16 = rem & 7;
            const uint32_t off = row * APITCH + c16 * 16;
            const __nv_bfloat16* src;
            uint32_t dst;
            if ((i >> 1) == 0)      { src = ph + pbase + (size_t)row * T + jt * 64 + c16 * 8; dst = sb + off; }
            else if ((i >> 1) == 1) { src = pl + pbase + (size_t)row * T + jt * 64 + c16 * 8; dst = sb + AARR + off; }
            else if ((i >> 1) == 2) { src = qh + vbase + (size_t)(jt * 64 + row) * D3 + c16 * 8; dst = sb + 2 * AARR + off; }
            else                    { src = ql + vbase + (size_t)(jt * 64 + row) * D3 + c16 * 8; dst = sb + 3 * AARR + off; }
            CP16(dst, src);
        }
        CP_COMMIT();
    };

    issue(0);

    for (int jt = 0; jt < nT; ++jt) {
        const int s = jt & 1;
        if (jt + 1 < nT) { issue(jt + 1); CP_WAIT(1); }
        else             { CP_WAIT(0); }
        __syncthreads();

        const uint32_t sPh = sbase + s * (4 * AARR);
        const uint32_t sPl = sPh + AARR;
        const uint32_t sVh = sPh + 2 * AARR;
        const uint32_t sVl = sPh + 3 * AARR;

        #pragma unroll
        for (int ks = 0; ks < 4; ks++) {
            const uint32_t kb = ks * 32;
            uint32_t a_h[4], a_l[4], b_h[4][2], b_l[4][2];
            const uint32_t aoff = (wm * 16 + (lane & 15)) * APITCH + kb + ((lane >> 4) << 4);
            LDSM4(a_h[0], a_h[1], a_h[2], a_h[3], sPh + aoff);
            LDSM4(a_l[0], a_l[1], a_l[2], a_l[3], sPl + aoff);
            #pragma unroll
            for (int nb = 0; nb < 2; nb++) {
                const int d0 = wn * 32 + nb * 16;
                // trans: threads 0-15 -> V rows ks*16+0..15 at dcol d0;
                //        threads 16-31 -> same rows at dcol d0+8
                const uint32_t off = (ks * 16 + (lane & 15)) * APITCH
                                   + d0 * 2 + ((lane >> 4) << 4);
                LDSM4T(b_h[2 * nb][0], b_h[2 * nb][1],
                       b_h[2 * nb + 1][0], b_h[2 * nb + 1][1], sVh + off);
                LDSM4T(b_l[2 * nb][0], b_l[2 * nb][1],
                       b_l[2 * nb + 1][0], b_l[2 * nb + 1][1], sVl + off);
            }
            #pragma unroll
            for (int ni = 0; ni < 4; ni++) {
                MMA_BF16(acc[ni], a_h, b_h[ni]);
                MMA_BF16(acc[ni], a_h, b_l[ni]);
                MMA_BF16(acc[ni], a_l, b_h[ni]);
            }
        }
        __syncthreads();
    }

    #pragma unroll
    for (int ni = 0; ni < 4; ni++) {
        const int r0 = wm * 16 + (lane >> 2);
        const int cc = wn * 32 + ni * 8 + ((lane & 3) << 1);
        const size_t g0 = ((size_t)b * T + it * 64 + r0) * D + h * DH + cc;
        const size_t g1 = ((size_t)b * T + it * 64 + r0 + 8) * D + h * DH + cc;
        __nv_bfloat162 h0, l0, h1, l1;
        split2(acc[ni][0], h0.x, l0.x); split2(acc[ni][1], h0.y, l0.y);
        split2(acc[ni][2], h1.x, l1.x); split2(acc[ni][3], h1.y, l1.y);
        *(__nv_bfloat162*)(oh + g0) = h0;
        *(__nv_bfloat162*)(ol + g0) = l0;
        *(__nv_bfloat162*)(oh + g1) = h1;
        *(__nv_bfloat162*)(ol + g1) = l1;
    }
}

// ---------------------------------------------------------------------------
// Launcher
// ---------------------------------------------------------------------------
extern "C" void kernel_launch(void* const* d_in, const int* in_sizes, int n_in,
                              void* d_out, int out_size)
{
    const int*   ids   = (const int*)  d_in[0];
    const float* tok   = (const float*)d_in[1];
    const float* pos   = (const float*)d_in[2];
    const float* ln1_s = (const float*)d_in[3];
    const float* ln1_b = (const float*)d_in[4];
    const float* Wqkv  = (const float*)d_in[5];
    const float* Wout  = (const float*)d_in[6];
    const float* ln2_s = (const float*)d_in[7];
    const float* ln2_b = (const float*)d_in[8];
    const float* W1    = (const float*)d_in[9];
    const float* W2    = (const float*)d_in[10];
    const float* lnf_s = (const float*)d_in[11];
    const float* lnf_b = (const float*)d_in[12];
    float* out = (float*)d_out;

    float *x, *sc;
    __nv_bfloat16 *qh, *ql, *ph, *pl, *ah, *al, *bh, *bl;
    __nv_bfloat16 *wqh, *wql, *woh, *wol, *w1h, *w1l, *w2h, *w2l;
    cudaGetSymbolAddress((void**)&x,   g_x);
    cudaGetSymbolAddress((void**)&sc,  g_sc);
    cudaGetSymbolAddress((void**)&qh,  g_qh);
    cudaGetSymbolAddress((void**)&ql,  g_ql);
    cudaGetSymbolAddress((void**)&ph,  g_ph);
    cudaGetSymbolAddress((void**)&pl,  g_pl);
    cudaGetSymbolAddress((void**)&ah,  g_ah);
    cudaGetSymbolAddress((void**)&al,  g_al);
    cudaGetSymbolAddress((void**)&bh,  g_bh);
    cudaGetSymbolAddress((void**)&bl,  g_bl);
    cudaGetSymbolAddress((void**)&wqh, g_wqkv_h);
    cudaGetSymbolAddress((void**)&wql, g_wqkv_l);
    cudaGetSymbolAddress((void**)&woh, g_wout_h);
    cudaGetSymbolAddress((void**)&wol, g_wout_l);
    cudaGetSymbolAddress((void**)&w1h, g_w1_h);
    cudaGetSymbolAddress((void**)&w1l, g_w1_l);
    cudaGetSymbolAddress((void**)&w2h, g_w2_h);
    cudaGetSymbolAddress((void**)&w2l, g_w2_l);

    cudaFuncSetAttribute(gemm_mma<0>, cudaFuncAttributeMaxDynamicSharedMemorySize, GEMM_SMEM);
    cudaFuncSetAttribute(gemm_mma<1>, cudaFuncAttributeMaxDynamicSharedMemorySize, GEMM_SMEM);
    cudaFuncSetAttribute(gemm_mma<2>, cudaFuncAttributeMaxDynamicSharedMemorySize, GEMM_SMEM);
    cudaFuncSetAttribute(gemm_mma<3>, cudaFuncAttributeMaxDynamicSharedMemorySize, GEMM_SMEM);
    cudaFuncSetAttribute(attnv_mma,   cudaFuncAttributeMaxDynamicSharedMemorySize, AV_SMEM);

    for (int l = 0; l < Lx; l++) {
        tsplit_kernel<<<dim3(D3 / 32, D / 32),  256>>>(Wqkv + (size_t)l * D * D3,
            wqh + (size_t)l * D3 * D,  wql + (size_t)l * D3 * D,  D,  D3);
        tsplit_kernel<<<dim3(D / 32, D / 32),   256>>>(Wout + (size_t)l * D * D,
            woh + (size_t)l * D * D,   wol + (size_t)l * D * D,   D,  D);
        tsplit_kernel<<<dim3(DFF / 32, D / 32), 256>>>(W1 + (size_t)l * D * DFF,
            w1h + (size_t)l * DFF * D, w1l + (size_t)l * DFF * D, D,  DFF);
        tsplit_kernel<<<dim3(D / 32, DFF / 32), 256>>>(W2 + (size_t)l * DFF * D,
            w2h + (size_t)l * D * DFF, w2l + (size_t)l * D * DFF, DFF, D);
    }

    embed_kernel<<<MR, 256>>>(ids, tok, pos, x);

    for (int l = 0; l < Lx; l++) {
        ln_split_kernel<<<MR, 256>>>(x, ln1_s + l * D, ln1_b + l * D, ah, al);
        gemm_mma<3><<<dim3(D3 / 128, MR / 128), 256, GEMM_SMEM>>>(
            ah, al, wqh + (size_t)l * D3 * D, wql + (size_t)l * D3 * D,
            nullptr, nullptr, qh, ql, D3, D);

        scores_mma<<<dim3(T / 64, T / 64, Bx * H), 256>>>(qh, ql, sc);
        softmax_kernel<<<Bx * H * T, 256>>>(sc, ph, pl);
        attnv_mma<<<dim3(T / 64, Bx * H), 256, AV_SMEM>>>(ph, pl, qh, ql, ah, al);

        gemm_mma<2><<<dim3(D / 128, MR / 128), 256, GEMM_SMEM>>>(
            ah, al, woh + (size_t)l * D * D, wol + (size_t)l * D * D,
            x, x, nullptr, nullptr, D, D);

        ln_split_kernel<<<MR, 256>>>(x, ln2_s + l * D, ln2_b + l * D, ah, al);
        gemm_mma<1><<<dim3(DFF / 128, MR / 128), 256, GEMM_SMEM>>>(
            ah, al, w1h + (size_t)l * DFF * D, w1l + (size_t)l * DFF * D,
            nullptr, nullptr, bh, bl, DFF, D);
        gemm_mma<2><<<dim3(D / 128, MR / 128), 256, GEMM_SMEM>>>(
            bh, bl, w2h + (size_t)l * D * DFF, w2l + (size_t)l * D * DFF,
            x, x, nullptr, nullptr, D, DFF);
    }

    ln_kernel<<<MR, 256>>>(x, lnf_s, lnf_b, out);
}

// round 9
// speedup vs baseline: 2.4342x; 1.0544x over previous
#include <cuda_runtime.h>
#include <cuda_bf16.h>
#include <math_constants.h>
#include <cstdint>

// ---------------------------------------------------------------------------
// Constants
// ---------------------------------------------------------------------------
namespace {
constexpr int Bx  = 2;
constexpr int T   = 1024;
constexpr int D   = 1024;
constexpr int H   = 16;
constexpr int Lx  = 6;
constexpr int DH  = 64;
constexpr int DFF = 2048;
constexpr int MR  = Bx * T;     // 2048
constexpr int D3  = 3 * D;      // 3072

// Big GEMM smem: 3 stages x 4 arrays x 128 rows x 144B pitch (BK=64)
constexpr int PITCH_B   = 144;                 // 64 bf16 (128B) + 16B pad
constexpr int ARR_B     = 128 * PITCH_B;       // 18432
constexpr int STG_B     = 4 * ARR_B;           // 73728
constexpr int NSTG      = 3;
constexpr int GEMM_SMEM = NSTG * STG_B;        // 221184

// Attention tiles: 64x64 bf16, 144B pitch
constexpr int APITCH    = 144;
constexpr int AARR      = 64 * APITCH;         // 9216
constexpr int SC_SMEM   = 4 * AARR;            // 36864 (static, 1 stage)
constexpr int AV_SMEM   = 2 * 4 * AARR;        // 73728 (dynamic, 2 stages)
}

// ---------------------------------------------------------------------------
// Scratch (device globals; allocation-free per harness rules)
// ---------------------------------------------------------------------------
__device__ float g_x  [MR * D];                        // residual stream
__device__ float g_sc [(size_t)Bx * H * T * T];        // fp32 scores
__device__ __align__(16) __nv_bfloat16 g_qh[MR * D3];  // qkv hi
__device__ __align__(16) __nv_bfloat16 g_ql[MR * D3];  // qkv lo
__device__ __align__(16) __nv_bfloat16 g_ph[(size_t)Bx * H * T * T]; // probs hi
__device__ __align__(16) __nv_bfloat16 g_pl[(size_t)Bx * H * T * T]; // probs lo
__device__ __align__(16) __nv_bfloat16 g_ah[MR * DFF];
__device__ __align__(16) __nv_bfloat16 g_al[MR * DFF];
__device__ __align__(16) __nv_bfloat16 g_bh[MR * DFF];
__device__ __align__(16) __nv_bfloat16 g_bl[MR * DFF];
// Transposed+split weights [N, K] bf16
__device__ __align__(16) __nv_bfloat16 g_wqkv_h[Lx * D3 * D];
__device__ __align__(16) __nv_bfloat16 g_wqkv_l[Lx * D3 * D];
__device__ __align__(16) __nv_bfloat16 g_wout_h[Lx * D * D];
__device__ __align__(16) __nv_bfloat16 g_wout_l[Lx * D * D];
__device__ __align__(16) __nv_bfloat16 g_w1_h  [Lx * DFF * D];
__device__ __align__(16) __nv_bfloat16 g_w1_l  [Lx * DFF * D];
__device__ __align__(16) __nv_bfloat16 g_w2_h  [Lx * D * DFF];
__device__ __align__(16) __nv_bfloat16 g_w2_l  [Lx * D * DFF];

// ---------------------------------------------------------------------------
// PTX helpers (baseline sm_80+)
// ---------------------------------------------------------------------------
__device__ __forceinline__ uint32_t smem_u32(const void* p) {
    uint32_t a;
    asm("{ .reg .u64 t; cvta.to.shared.u64 t, %1; cvt.u32.u64 %0, t; }"
        : "=r"(a) : "l"(p));
    return a;
}
#define CP16(dst, src)                                                         \
    asm volatile("cp.async.cg.shared.global [%0], [%1], 16;"                   \
                 :: "r"(dst), "l"(src))
#define CP_COMMIT()  asm volatile("cp.async.commit_group;" ::: "memory")
#define CP_WAIT(n)   asm volatile("cp.async.wait_group %0;" :: "n"(n) : "memory")

#define LDSM4(r0, r1, r2, r3, addr)                                            \
    asm volatile("ldmatrix.sync.aligned.m8n8.x4.shared.b16 {%0,%1,%2,%3}, [%4];" \
                 : "=r"(r0), "=r"(r1), "=r"(r2), "=r"(r3) : "r"(addr))
#define LDSM4T(r0, r1, r2, r3, addr)                                           \
    asm volatile("ldmatrix.sync.aligned.m8n8.x4.trans.shared.b16 {%0,%1,%2,%3}, [%4];" \
                 : "=r"(r0), "=r"(r1), "=r"(r2), "=r"(r3) : "r"(addr))

#define MMA_BF16(c, a, b)                                                      \
    asm volatile("mma.sync.aligned.m16n8k16.row.col.f32.bf16.bf16.f32 "        \
                 "{%0,%1,%2,%3}, {%4,%5,%6,%7}, {%8,%9}, {%0,%1,%2,%3};"       \
                 : "+f"((c)[0]), "+f"((c)[1]), "+f"((c)[2]), "+f"((c)[3])      \
                 : "r"((a)[0]), "r"((a)[1]), "r"((a)[2]), "r"((a)[3]),         \
                   "r"((b)[0]), "r"((b)[1]))

__device__ __forceinline__ void split2(float v, __nv_bfloat16& h, __nv_bfloat16& l) {
    h = __float2bfloat16(v);
    l = __float2bfloat16(v - __bfloat162float(h));
}
__device__ __forceinline__ float gelu_exact(float v) {
    return 0.5f * v * (1.0f + erff(v * 0.70710678118654752f));
}

// ---------------------------------------------------------------------------
// Embedding
// ---------------------------------------------------------------------------
__global__ __launch_bounds__(256) void embed_kernel(
    const int* __restrict__ ids, const float* __restrict__ tok,
    const float* __restrict__ pos, float* __restrict__ x)
{
    const int row = blockIdx.x;
    const int t   = row & (T - 1);
    const int id  = ids[row];
    const float4* te = (const float4*)(tok + (size_t)id * D);
    const float4* pe = (const float4*)(pos + (size_t)t  * D);
    float4*       xr = (float4*)(x + (size_t)row * D);
    const int c = threadIdx.x;
    float4 a = te[c], b = pe[c];
    xr[c] = make_float4(a.x + b.x, a.y + b.y, a.z + b.z, a.w + b.w);
}

// ---------------------------------------------------------------------------
// LayerNorm
// ---------------------------------------------------------------------------
__device__ __forceinline__ void ln_stats(const float4 v, int tid,
                                         float& mean, float& rstd,
                                         float* r1, float* r2)
{
    float sum = v.x + v.y + v.z + v.w;
    float sq  = v.x * v.x + v.y * v.y + v.z * v.z + v.w * v.w;
    r1[tid] = sum; r2[tid] = sq;
    __syncthreads();
    #pragma unroll
    for (int st = 128; st > 0; st >>= 1) {
        if (tid < st) { r1[tid] += r1[tid + st]; r2[tid] += r2[tid + st]; }
        __syncthreads();
    }
    mean = r1[0] * (1.0f / D);
    const float var = r2[0] * (1.0f / D) - mean * mean;
    rstd = rsqrtf(var + 1e-5f);
}

__global__ __launch_bounds__(256) void ln_kernel(
    const float* __restrict__ x, const float* __restrict__ s,
    const float* __restrict__ b, float* __restrict__ out)
{
    const int row = blockIdx.x, tid = threadIdx.x;
    const float4 v = ((const float4*)(x + (size_t)row * D))[tid];
    __shared__ float r1[256], r2[256];
    float mean, rstd;
    ln_stats(v, tid, mean, rstd, r1, r2);
    const float4 sv = ((const float4*)s)[tid];
    const float4 bv = ((const float4*)b)[tid];
    float4 o;
    o.x = (v.x - mean) * rstd * sv.x + bv.x;
    o.y = (v.y - mean) * rstd * sv.y + bv.y;
    o.z = (v.z - mean) * rstd * sv.z + bv.z;
    o.w = (v.w - mean) * rstd * sv.w + bv.w;
    ((float4*)(out + (size_t)row * D))[tid] = o;
}

__global__ __launch_bounds__(256) void ln_split_kernel(
    const float* __restrict__ x, const float* __restrict__ s,
    const float* __restrict__ b,
    __nv_bfloat16* __restrict__ ah, __nv_bfloat16* __restrict__ al)
{
    const int row = blockIdx.x, tid = threadIdx.x;
    const float4 v = ((const float4*)(x + (size_t)row * D))[tid];
    __shared__ float r1[256], r2[256];
    float mean, rstd;
    ln_stats(v, tid, mean, rstd, r1, r2);
    const float4 sv = ((const float4*)s)[tid];
    const float4 bv = ((const float4*)b)[tid];
    float o[4];
    o[0] = (v.x - mean) * rstd * sv.x + bv.x;
    o[1] = (v.y - mean) * rstd * sv.y + bv.y;
    o[2] = (v.z - mean) * rstd * sv.z + bv.z;
    o[3] = (v.w - mean) * rstd * sv.w + bv.w;
    const size_t base = (size_t)row * D + (tid << 2);
    __nv_bfloat162 h01, h23, l01, l23;
    split2(o[0], h01.x, l01.x); split2(o[1], h01.y, l01.y);
    split2(o[2], h23.x, l23.x); split2(o[3], h23.y, l23.y);
    *(__nv_bfloat162*)(ah + base)     = h01;
    *(__nv_bfloat162*)(ah + base + 2) = h23;
    *(__nv_bfloat162*)(al + base)     = l01;
    *(__nv_bfloat162*)(al + base + 2) = l23;
}

// ---------------------------------------------------------------------------
// Weight prep
// ---------------------------------------------------------------------------
__global__ __launch_bounds__(256) void tsplit_kernel(
    const float* __restrict__ W, __nv_bfloat16* __restrict__ oh,
    __nv_bfloat16* __restrict__ ol, int Kd, int Nd)
{
    __shared__ float s[32][33];
    const int n0 = blockIdx.x * 32, k0 = blockIdx.y * 32;
    const int tx = threadIdx.x & 31, ty = threadIdx.x >> 5;
    #pragma unroll
    for (int j = 0; j < 4; j++)
        s[ty + j * 8][tx] = W[(size_t)(k0 + ty + j * 8) * Nd + n0 + tx];
    __syncthreads();
    #pragma unroll
    for (int j = 0; j < 4; j++) {
        const float v = s[tx][ty + j * 8];
        __nv_bfloat16 h, l;
        split2(v, h, l);
        const size_t idx = (size_t)(n0 + ty + j * 8) * Kd + k0 + tx;
        oh[idx] = h; ol[idx] = l;
    }
}

// ---------------------------------------------------------------------------
// Warp-MMA GEMM: C[M,N] = A[M,K] * B[N,K]^T, 3-term bf16 split, fp32 accum.
// CTA tile 128x128, BK=64, 8 warps (4m x 2n), 3-stage cp.async pipeline.
// EPI: 0 fp32, 1 GELU->split bf16, 2 residual add fp32, 3 plain split bf16.
// ---------------------------------------------------------------------------
template <int EPI>
__global__ __launch_bounds__(256) void gemm_mma(
    const __nv_bfloat16* __restrict__ Ah, const __nv_bfloat16* __restrict__ Al,
    const __nv_bfloat16* __restrict__ Bh, const __nv_bfloat16* __restrict__ Bl,
    const float* __restrict__ R, float* __restrict__ Cf,
    __nv_bfloat16* __restrict__ Ch, __nv_bfloat16* __restrict__ Cl,
    int Ndim, int Kdim)
{
    extern __shared__ char smem[];
    const uint32_t sbase = smem_u32(smem);
    const int tid = threadIdx.x, wid = tid >> 5, lane = tid & 31;
    const int row0 = blockIdx.y << 7, col0 = blockIdx.x << 7;
    const int wm = wid & 3, wn = wid >> 2;
    const int nC = Kdim >> 6;        // BK = 64

    float acc[2][8][4];
    #pragma unroll
    for (int a = 0; a < 2; a++)
        #pragma unroll
        for (int b = 0; b < 8; b++)
            #pragma unroll
            for (int c = 0; c < 4; c++) acc[a][b][c] = 0.f;

    // ---- issue chunk c loads into stage (c % 3): 16 CP16 per thread ----
    auto issue = [&](int c) {
        const int s = c % NSTG;
        const int k0 = c << 6;
        const uint32_t sb = sbase + s * STG_B;
        #pragma unroll
        for (int i = 0; i < 16; i++) {
            const int arr = i >> 2;
            const int rem = tid + ((i & 3) << 8);
            const int row = rem >> 3, c16 = rem & 7;
            const uint32_t dst = sb + arr * ARR_B + row * PITCH_B + c16 * 16;
            const __nv_bfloat16* src;
            if (arr == 0)      src = Ah + (size_t)(row0 + row) * Kdim + k0 + c16 * 8;
            else if (arr == 1) src = Al + (size_t)(row0 + row) * Kdim + k0 + c16 * 8;
            else if (arr == 2) src = Bh + (size_t)(col0 + row) * Kdim + k0 + c16 * 8;
            else               src = Bl + (size_t)(col0 + row) * Kdim + k0 + c16 * 8;
            CP16(dst, src);
        }
        CP_COMMIT();
    };

    issue(0);
    if (nC > 1) issue(1);

    for (int c = 0; c < nC; ++c) {
        const int s = c % NSTG;
        if (c + 2 < nC)      { issue(c + 2); CP_WAIT(2); }
        else if (c + 1 < nC) { CP_WAIT(1); }
        else                 { CP_WAIT(0); }
        __syncthreads();

        const uint32_t sa_h = sbase + s * STG_B;
        const uint32_t sa_l = sa_h + ARR_B;
        const uint32_t sb_h = sa_h + 2 * ARR_B;
        const uint32_t sb_l = sa_h + 3 * ARR_B;

        #pragma unroll
        for (int ks = 0; ks < 4; ks++) {
            uint32_t a_h[2][4], a_l[2][4], b_h[8][2], b_l[8][2];
            const uint32_t kb = ks * 32;     // 16 bf16 = 32 bytes
            #pragma unroll
            for (int mi = 0; mi < 2; mi++) {
                const int mrow = wm * 32 + mi * 16 + (lane & 15);
                const uint32_t off = mrow * PITCH_B + kb + ((lane >> 4) << 4);
                LDSM4(a_h[mi][0], a_h[mi][1], a_h[mi][2], a_h[mi][3], sa_h + off);
                LDSM4(a_l[mi][0], a_l[mi][1], a_l[mi][2], a_l[mi][3], sa_l + off);
            }
            #pragma unroll
            for (int nb = 0; nb < 4; nb++) {
                const int nrow = wn * 64 + nb * 16 + (((lane >> 4) & 1) << 3) + (lane & 7);
                const uint32_t off = nrow * PITCH_B + kb + (((lane >> 3) & 1) << 4);
                LDSM4(b_h[2 * nb][0], b_h[2 * nb][1],
                      b_h[2 * nb + 1][0], b_h[2 * nb + 1][1], sb_h + off);
                LDSM4(b_l[2 * nb][0], b_l[2 * nb][1],
                      b_l[2 * nb + 1][0], b_l[2 * nb + 1][1], sb_l + off);
            }
            #pragma unroll
            for (int mi = 0; mi < 2; mi++)
                #pragma unroll
                for (int ni = 0; ni < 8; ni++) {
                    MMA_BF16(acc[mi][ni], a_h[mi], b_h[ni]);
                    MMA_BF16(acc[mi][ni], a_h[mi], b_l[ni]);
                    MMA_BF16(acc[mi][ni], a_l[mi], b_h[ni]);
                }
        }
        __syncthreads();
    }

    #pragma unroll
    for (int mi = 0; mi < 2; mi++) {
        #pragma unroll
        for (int ni = 0; ni < 8; ni++) {
            const int r0 = row0 + wm * 32 + mi * 16 + (lane >> 2);
            const int r1 = r0 + 8;
            const int cc = col0 + wn * 64 + ni * 8 + ((lane & 3) << 1);
            const float* a = acc[mi][ni];
            if (EPI == 0) {
                *(float2*)(Cf + (size_t)r0 * Ndim + cc) = make_float2(a[0], a[1]);
                *(float2*)(Cf + (size_t)r1 * Ndim + cc) = make_float2(a[2], a[3]);
            } else if (EPI == 2) {
                const float2 q0 = *(const float2*)(R + (size_t)r0 * Ndim + cc);
                const float2 q1 = *(const float2*)(R + (size_t)r1 * Ndim + cc);
                *(float2*)(Cf + (size_t)r0 * Ndim + cc) = make_float2(a[0] + q0.x, a[1] + q0.y);
                *(float2*)(Cf + (size_t)r1 * Ndim + cc) = make_float2(a[2] + q1.x, a[3] + q1.y);
            } else {
                float v0 = a[0], v1 = a[1], v2 = a[2], v3 = a[3];
                if (EPI == 1) { v0 = gelu_exact(v0); v1 = gelu_exact(v1);
                                v2 = gelu_exact(v2); v3 = gelu_exact(v3); }
                __nv_bfloat162 h0, l0, h1, l1;
                split2(v0, h0.x, l0.x); split2(v1, h0.y, l0.y);
                split2(v2, h1.x, l1.x); split2(v3, h1.y, l1.y);
                *(__nv_bfloat162*)(Ch + (size_t)r0 * Ndim + cc) = h0;
                *(__nv_bfloat162*)(Cl + (size_t)r0 * Ndim + cc) = l0;
                *(__nv_bfloat162*)(Ch + (size_t)r1 * Ndim + cc) = h1;
                *(__nv_bfloat162*)(Cl + (size_t)r1 * Ndim + cc) = l1;
            }
        }
    }
}

// ---------------------------------------------------------------------------
// Scores: S[bh,it*64+,jt*64+] = (Q.K^T)/8 via mma, 3-term split. 1 stage.
// ---------------------------------------------------------------------------
__global__ __launch_bounds__(256) void scores_mma(
    const __nv_bfloat16* __restrict__ qh, const __nv_bfloat16* __restrict__ ql,
    float* __restrict__ sc)
{
    const int jt = blockIdx.x, it = blockIdx.y;
    if (jt > it) return;
    const int bh = blockIdx.z, b = bh >> 4, h = bh & 15;
    const int tid = threadIdx.x, wid = tid >> 5, lane = tid & 31;
    const int wm = wid & 3, wn = wid >> 2;

    __shared__ __align__(16) char smem[SC_SMEM];
    const uint32_t sbase = smem_u32(smem);
    const uint32_t sQh = sbase, sQl = sbase + AARR;
    const uint32_t sKh = sbase + 2 * AARR, sKl = sbase + 3 * AARR;

    const size_t qbase = ((size_t)b * T + it * 64) * D3 + h * DH;
    const size_t kbase = ((size_t)b * T + jt * 64) * D3 + D + h * DH;

    #pragma unroll
    for (int i = 0; i < 8; i++) {
        const int rem = tid + ((i & 1) << 8);
        const int row = rem >> 3, c16 = rem & 7;
        const uint32_t off = row * APITCH + c16 * 16;
        const __nv_bfloat16* src;
        uint32_t dst;
        if ((i >> 1) == 0)      { src = qh + qbase + (size_t)row * D3 + c16 * 8; dst = sQh + off; }
        else if ((i >> 1) == 1) { src = ql + qbase + (size_t)row * D3 + c16 * 8; dst = sQl + off; }
        else if ((i >> 1) == 2) { src = qh + kbase + (size_t)row * D3 + c16 * 8; dst = sKh + off; }
        else                    { src = ql + kbase + (size_t)row * D3 + c16 * 8; dst = sKl + off; }
        CP16(dst, src);
    }
    CP_COMMIT();
    CP_WAIT(0);
    __syncthreads();

    float acc[4][4] = {};
    #pragma unroll
    for (int ks = 0; ks < 4; ks++) {
        const uint32_t kb = ks * 32;
        uint32_t a_h[4], a_l[4], b_h[4][2], b_l[4][2];
        const uint32_t aoff = (wm * 16 + (lane & 15)) * APITCH + kb + ((lane >> 4) << 4);
        LDSM4(a_h[0], a_h[1], a_h[2], a_h[3], sQh + aoff);
        LDSM4(a_l[0], a_l[1], a_l[2], a_l[3], sQl + aoff);
        #pragma unroll
        for (int nb = 0; nb < 2; nb++) {
            const int nrow = wn * 32 + nb * 16 + (((lane >> 4) & 1) << 3) + (lane & 7);
            const uint32_t off = nrow * APITCH + kb + (((lane >> 3) & 1) << 4);
            LDSM4(b_h[2 * nb][0], b_h[2 * nb][1],
                  b_h[2 * nb + 1][0], b_h[2 * nb + 1][1], sKh + off);
            LDSM4(b_l[2 * nb][0], b_l[2 * nb][1],
                  b_l[2 * nb + 1][0], b_l[2 * nb + 1][1], sKl + off);
        }
        #pragma unroll
        for (int ni = 0; ni < 4; ni++) {
            MMA_BF16(acc[ni], a_h, b_h[ni]);
            MMA_BF16(acc[ni], a_h, b_l[ni]);
            MMA_BF16(acc[ni], a_l, b_h[ni]);
        }
    }

    float* out = sc + (size_t)bh * T * T;
    #pragma unroll
    for (int ni = 0; ni < 4; ni++) {
        const int r0 = it * 64 + wm * 16 + (lane >> 2);
        const int cc = jt * 64 + wn * 32 + ni * 8 + ((lane & 3) << 1);
        *(float2*)(out + (size_t)r0 * T + cc) =
            make_float2(acc[ni][0] * 0.125f, acc[ni][1] * 0.125f);
        *(float2*)(out + (size_t)(r0 + 8) * T + cc) =
            make_float2(acc[ni][2] * 0.125f, acc[ni][3] * 0.125f);
    }
}

// ---------------------------------------------------------------------------
// Causal softmax: fp32 scores -> split bf16 probs, zero-filled to tile edge.
// ---------------------------------------------------------------------------
__global__ __launch_bounds__(256) void softmax_kernel(
    const float* __restrict__ sc,
    __nv_bfloat16* __restrict__ ph, __nv_bfloat16* __restrict__ pl)
{
    const int g = blockIdx.x;
    const int i = g & (T - 1);
    const int n = i + 1;
    const int nn = (i & ~63) + 64;
    const float* row = sc + (size_t)g * T;
    __nv_bfloat16* rh = ph + (size_t)g * T;
    __nv_bfloat16* rl = pl + (size_t)g * T;
    const int tid = threadIdx.x;
    __shared__ float red[256];

    float m = -CUDART_INF_F;
    for (int j = tid; j < n; j += 256) m = fmaxf(m, row[j]);
    red[tid] = m; __syncthreads();
    #pragma unroll
    for (int st = 128; st > 0; st >>= 1) {
        if (tid < st) red[tid] = fmaxf(red[tid], red[tid + st]);
        __syncthreads();
    }
    m = red[0];
    __syncthreads();

    float sum = 0.f;
    for (int j = tid; j < n; j += 256) sum += expf(row[j] - m);
    red[tid] = sum; __syncthreads();
    #pragma unroll
    for (int st = 128; st > 0; st >>= 1) {
        if (tid < st) red[tid] += red[tid + st];
        __syncthreads();
    }
    const float inv = 1.0f / red[0];

    for (int j = tid; j < nn; j += 256) {
        float p = (j < n) ? expf(row[j] - m) * inv : 0.0f;
        __nv_bfloat16 hv, lv;
        split2(p, hv, lv);
        rh[j] = hv; rl[j] = lv;
    }
}

// ---------------------------------------------------------------------------
// O = P @ V via mma (A=P non-trans; B=V via ldmatrix.trans), 3-term split.
// Block: (it, bh). Double-buffered over jt tiles.
// ---------------------------------------------------------------------------
__global__ __launch_bounds__(256) void attnv_mma(
    const __nv_bfloat16* __restrict__ ph, const __nv_bfloat16* __restrict__ pl,
    const __nv_bfloat16* __restrict__ qh, const __nv_bfloat16* __restrict__ ql,
    __nv_bfloat16* __restrict__ oh, __nv_bfloat16* __restrict__ ol)
{
    extern __shared__ char smem[];
    const uint32_t sbase = smem_u32(smem);
    const int it = blockIdx.x, bh = blockIdx.y, b = bh >> 4, h = bh & 15;
    const int tid = threadIdx.x, wid = tid >> 5, lane = tid & 31;
    const int wm = wid & 3, wn = wid >> 2;

    const size_t pbase = (size_t)bh * T * T + (size_t)(it * 64) * T;
    const size_t vbase = (size_t)b * T * D3 + 2 * D + h * DH;
    const int nT = it + 1;

    float acc[4][4] = {};

    auto issue = [&](int jt) {
        const int s = jt & 1;
        const uint32_t sb = sbase + s * (4 * AARR);
        #pragma unroll
        for (int i = 0; i < 8; i++) {
            const int rem = tid + ((i & 1) << 8);
            const int row = rem >> 3, c16 = rem & 7;
            const uint32_t off = row * APITCH + c16 * 16;
            const __nv_bfloat16* src;
            uint32_t dst;
            if ((i >> 1) == 0)      { src = ph + pbase + (size_t)row * T + jt * 64 + c16 * 8; dst = sb + off; }
            else if ((i >> 1) == 1) { src = pl + pbase + (size_t)row * T + jt * 64 + c16 * 8; dst = sb + AARR + off; }
            else if ((i >> 1) == 2) { src = qh + vbase + (size_t)(jt * 64 + row) * D3 + c16 * 8; dst = sb + 2 * AARR + off; }
            else                    { src = ql + vbase + (size_t)(jt * 64 + row) * D3 + c16 * 8; dst = sb + 3 * AARR + off; }
            CP16(dst, src);
        }
        CP_COMMIT();
    };

    issue(0);

    for (int jt = 0; jt < nT; ++jt) {
        const int s = jt & 1;
        if (jt + 1 < nT) { issue(jt + 1); CP_WAIT(1); }
        else             { CP_WAIT(0); }
        __syncthreads();

        const uint32_t sPh = sbase + s * (4 * AARR);
        const uint32_t sPl = sPh + AARR;
        const uint32_t sVh = sPh + 2 * AARR;
        const uint32_t sVl = sPh + 3 * AARR;

        #pragma unroll
        for (int ks = 0; ks < 4; ks++) {
            const uint32_t kb = ks * 32;
            uint32_t a_h[4], a_l[4], b_h[4][2], b_l[4][2];
            const uint32_t aoff = (wm * 16 + (lane & 15)) * APITCH + kb + ((lane >> 4) << 4);
            LDSM4(a_h[0], a_h[1], a_h[2], a_h[3], sPh + aoff);
            LDSM4(a_l[0], a_l[1], a_l[2], a_l[3], sPl + aoff);
            #pragma unroll
            for (int nb = 0; nb < 2; nb++) {
                const int d0 = wn * 32 + nb * 16;
                const uint32_t off = (ks * 16 + (lane & 15)) * APITCH
                                   + d0 * 2 + ((lane >> 4) << 4);
                LDSM4T(b_h[2 * nb][0], b_h[2 * nb][1],
                       b_h[2 * nb + 1][0], b_h[2 * nb + 1][1], sVh + off);
                LDSM4T(b_l[2 * nb][0], b_l[2 * nb][1],
                       b_l[2 * nb + 1][0], b_l[2 * nb + 1][1], sVl + off);
            }
            #pragma unroll
            for (int ni = 0; ni < 4; ni++) {
                MMA_BF16(acc[ni], a_h, b_h[ni]);
                MMA_BF16(acc[ni], a_h, b_l[ni]);
                MMA_BF16(acc[ni], a_l, b_h[ni]);
            }
        }
        __syncthreads();
    }

    #pragma unroll
    for (int ni = 0; ni < 4; ni++) {
        const int r0 = wm * 16 + (lane >> 2);
        const int cc = wn * 32 + ni * 8 + ((lane & 3) << 1);
        const size_t g0 = ((size_t)b * T + it * 64 + r0) * D + h * DH + cc;
        const size_t g1 = ((size_t)b * T + it * 64 + r0 + 8) * D + h * DH + cc;
        __nv_bfloat162 h0, l0, h1, l1;
        split2(acc[ni][0], h0.x, l0.x); split2(acc[ni][1], h0.y, l0.y);
        split2(acc[ni][2], h1.x, l1.x); split2(acc[ni][3], h1.y, l1.y);
        *(__nv_bfloat162*)(oh + g0) = h0;
        *(__nv_bfloat162*)(ol + g0) = l0;
        *(__nv_bfloat162*)(oh + g1) = h1;
        *(__nv_bfloat162*)(ol + g1) = l1;
    }
}

// ---------------------------------------------------------------------------
// Launcher
// ---------------------------------------------------------------------------
extern "C" void kernel_launch(void* const* d_in, const int* in_sizes, int n_in,
                              void* d_out, int out_size)
{
    const int*   ids   = (const int*)  d_in[0];
    const float* tok   = (const float*)d_in[1];
    const float* pos   = (const float*)d_in[2];
    const float* ln1_s = (const float*)d_in[3];
    const float* ln1_b = (const float*)d_in[4];
    const float* Wqkv  = (const float*)d_in[5];
    const float* Wout  = (const float*)d_in[6];
    const float* ln2_s = (const float*)d_in[7];
    const float* ln2_b = (const float*)d_in[8];
    const float* W1    = (const float*)d_in[9];
    const float* W2    = (const float*)d_in[10];
    const float* lnf_s = (const float*)d_in[11];
    const float* lnf_b = (const float*)d_in[12];
    float* out = (float*)d_out;

    float *x, *sc;
    __nv_bfloat16 *qh, *ql, *ph, *pl, *ah, *al, *bh, *bl;
    __nv_bfloat16 *wqh, *wql, *woh, *wol, *w1h, *w1l, *w2h, *w2l;
    cudaGetSymbolAddress((void**)&x,   g_x);
    cudaGetSymbolAddress((void**)&sc,  g_sc);
    cudaGetSymbolAddress((void**)&qh,  g_qh);
    cudaGetSymbolAddress((void**)&ql,  g_ql);
    cudaGetSymbolAddress((void**)&ph,  g_ph);
    cudaGetSymbolAddress((void**)&pl,  g_pl);
    cudaGetSymbolAddress((void**)&ah,  g_ah);
    cudaGetSymbolAddress((void**)&al,  g_al);
    cudaGetSymbolAddress((void**)&bh,  g_bh);
    cudaGetSymbolAddress((void**)&bl,  g_bl);
    cudaGetSymbolAddress((void**)&wqh, g_wqkv_h);
    cudaGetSymbolAddress((void**)&wql, g_wqkv_l);
    cudaGetSymbolAddress((void**)&woh, g_wout_h);
    cudaGetSymbolAddress((void**)&wol, g_wout_l);
    cudaGetSymbolAddress((void**)&w1h, g_w1_h);
    cudaGetSymbolAddress((void**)&w1l, g_w1_l);
    cudaGetSymbolAddress((void**)&w2h, g_w2_h);
    cudaGetSymbolAddress((void**)&w2l, g_w2_l);

    cudaFuncSetAttribute(gemm_mma<0>, cudaFuncAttributeMaxDynamicSharedMemorySize, GEMM_SMEM);
    cudaFuncSetAttribute(gemm_mma<1>, cudaFuncAttributeMaxDynamicSharedMemorySize, GEMM_SMEM);
    cudaFuncSetAttribute(gemm_mma<2>, cudaFuncAttributeMaxDynamicSharedMemorySize, GEMM_SMEM);
    cudaFuncSetAttribute(gemm_mma<3>, cudaFuncAttributeMaxDynamicSharedMemorySize, GEMM_SMEM);
    cudaFuncSetAttribute(attnv_mma,   cudaFuncAttributeMaxDynamicSharedMemorySize, AV_SMEM);

    for (int l = 0; l < Lx; l++) {
        tsplit_kernel<<<dim3(D3 / 32, D / 32),  256>>>(Wqkv + (size_t)l * D * D3,
            wqh + (size_t)l * D3 * D,  wql + (size_t)l * D3 * D,  D,  D3);
        tsplit_kernel<<<dim3(D / 32, D / 32),   256>>>(Wout + (size_t)l * D * D,
            woh + (size_t)l * D * D,   wol + (size_t)l * D * D,   D,  D);
        tsplit_kernel<<<dim3(DFF / 32, D / 32), 256>>>(W1 + (size_t)l * D * DFF,
            w1h + (size_t)l * DFF * D, w1l + (size_t)l * DFF * D, D,  DFF);
        tsplit_kernel<<<dim3(D / 32, DFF / 32), 256>>>(W2 + (size_t)l * DFF * D,
            w2h + (size_t)l * D * DFF, w2l + (size_t)l * D * DFF, DFF, D);
    }

    embed_kernel<<<MR, 256>>>(ids, tok, pos, x);

    for (int l = 0; l < Lx; l++) {
        ln_split_kernel<<<MR, 256>>>(x, ln1_s + l * D, ln1_b + l * D, ah, al);
        gemm_mma<3><<<dim3(D3 / 128, MR / 128), 256, GEMM_SMEM>>>(
            ah, al, wqh + (size_t)l * D3 * D, wql + (size_t)l * D3 * D,
            nullptr, nullptr, qh, ql, D3, D);

        scores_mma<<<dim3(T / 64, T / 64, Bx * H), 256>>>(qh, ql, sc);
        softmax_kernel<<<Bx * H * T, 256>>>(sc, ph, pl);
        attnv_mma<<<dim3(T / 64, Bx * H), 256, AV_SMEM>>>(ph, pl, qh, ql, ah, al);

        gemm_mma<2><<<dim3(D / 128, MR / 128), 256, GEMM_SMEM>>>(
            ah, al, woh + (size_t)l * D * D, wol + (size_t)l * D * D,
            x, x, nullptr, nullptr, D, D);

        ln_split_kernel<<<MR, 256>>>(x, ln2_s + l * D, ln2_b + l * D, ah, al);
        gemm_mma<1><<<dim3(DFF / 128, MR / 128), 256, GEMM_SMEM>>>(
            ah, al, w1h + (size_t)l * DFF * D, w1l + (size_t)l * DFF * D,
            nullptr, nullptr, bh, bl, DFF, D);
        gemm_mma<2><<<dim3(D / 128, MR / 128), 256, GEMM_SMEM>>>(
            bh, bl, w2h + (size_t)l * D * DFF, w2l + (size_t)l * D * DFF,
            x, x, nullptr, nullptr, D, DFF);
    }

    ln_kernel<<<MR, 256>>>(x, lnf_s, lnf_b, out);
}

// round 10
// speedup vs baseline: 2.8103x; 1.1545x over previous
#include <cuda_runtime.h>
#include <cuda_bf16.h>
#include <math_constants.h>
#include <cstdint>

// ---------------------------------------------------------------------------
// Constants
// ---------------------------------------------------------------------------
namespace {
constexpr int Bx  = 2;
constexpr int T   = 1024;
constexpr int D   = 1024;
constexpr int H   = 16;
constexpr int Lx  = 6;
constexpr int DH  = 64;
constexpr int DFF = 2048;
constexpr int MR  = Bx * T;     // 2048
constexpr int D3  = 3 * D;      // 3072

// Big GEMM smem: 3 stages x 4 arrays x 128 rows x 144B pitch (BK=64)
constexpr int PITCH_B   = 144;
constexpr int ARR_B     = 128 * PITCH_B;       // 18432
constexpr int STG_B     = 4 * ARR_B;           // 73728
constexpr int NSTG      = 3;
constexpr int GEMM_SMEM = NSTG * STG_B;        // 221184

// Flash attention: Q block 128 rows, KV tiles 64 rows, 144B pitch
constexpr int APITCH    = 144;
constexpr int AARR      = 64 * APITCH;         // 9216  (64x64 bf16 tile)
constexpr int QARR      = 128 * APITCH;        // 18432 (128x64 bf16 tile)
constexpr int KVSTG     = 4 * AARR;            // 36864 (Kh,Kl,Vh,Vl)
constexpr int FL_SMEM   = 2 * QARR + 2 * KVSTG; // 110592
}

// ---------------------------------------------------------------------------
// Scratch (device globals; allocation-free per harness rules)
// ---------------------------------------------------------------------------
__device__ float g_x  [MR * D];                        // residual stream
__device__ __align__(16) __nv_bfloat16 g_qh[MR * D3];  // qkv hi
__device__ __align__(16) __nv_bfloat16 g_ql[MR * D3];  // qkv lo
__device__ __align__(16) __nv_bfloat16 g_ah[MR * DFF];
__device__ __align__(16) __nv_bfloat16 g_al[MR * DFF];
__device__ __align__(16) __nv_bfloat16 g_bh[MR * DFF];
__device__ __align__(16) __nv_bfloat16 g_bl[MR * DFF];
// Transposed+split weights [N, K] bf16
__device__ __align__(16) __nv_bfloat16 g_wqkv_h[Lx * D3 * D];
__device__ __align__(16) __nv_bfloat16 g_wqkv_l[Lx * D3 * D];
__device__ __align__(16) __nv_bfloat16 g_wout_h[Lx * D * D];
__device__ __align__(16) __nv_bfloat16 g_wout_l[Lx * D * D];
__device__ __align__(16) __nv_bfloat16 g_w1_h  [Lx * DFF * D];
__device__ __align__(16) __nv_bfloat16 g_w1_l  [Lx * DFF * D];
__device__ __align__(16) __nv_bfloat16 g_w2_h  [Lx * D * DFF];
__device__ __align__(16) __nv_bfloat16 g_w2_l  [Lx * D * DFF];

// ---------------------------------------------------------------------------
// PTX helpers (baseline sm_80+)
// ---------------------------------------------------------------------------
__device__ __forceinline__ uint32_t smem_u32(const void* p) {
    uint32_t a;
    asm("{ .reg .u64 t; cvta.to.shared.u64 t, %1; cvt.u32.u64 %0, t; }"
        : "=r"(a) : "l"(p));
    return a;
}
#define CP16(dst, src)                                                         \
    asm volatile("cp.async.cg.shared.global [%0], [%1], 16;"                   \
                 :: "r"(dst), "l"(src))
#define CP_COMMIT()  asm volatile("cp.async.commit_group;" ::: "memory")
#define CP_WAIT(n)   asm volatile("cp.async.wait_group %0;" :: "n"(n) : "memory")

#define LDSM4(r0, r1, r2, r3, addr)                                            \
    asm volatile("ldmatrix.sync.aligned.m8n8.x4.shared.b16 {%0,%1,%2,%3}, [%4];" \
                 : "=r"(r0), "=r"(r1), "=r"(r2), "=r"(r3) : "r"(addr))
#define LDSM4T(r0, r1, r2, r3, addr)                                           \
    asm volatile("ldmatrix.sync.aligned.m8n8.x4.trans.shared.b16 {%0,%1,%2,%3}, [%4];" \
                 : "=r"(r0), "=r"(r1), "=r"(r2), "=r"(r3) : "r"(addr))

#define MMA_BF16(c, a, b)                                                      \
    asm volatile("mma.sync.aligned.m16n8k16.row.col.f32.bf16.bf16.f32 "        \
                 "{%0,%1,%2,%3}, {%4,%5,%6,%7}, {%8,%9}, {%0,%1,%2,%3};"       \
                 : "+f"((c)[0]), "+f"((c)[1]), "+f"((c)[2]), "+f"((c)[3])      \
                 : "r"((a)[0]), "r"((a)[1]), "r"((a)[2]), "r"((a)[3]),         \
                   "r"((b)[0]), "r"((b)[1]))

__device__ __forceinline__ void split2(float v, __nv_bfloat16& h, __nv_bfloat16& l) {
    h = __float2bfloat16(v);
    l = __float2bfloat16(v - __bfloat162float(h));
}
__device__ __forceinline__ uint32_t pack_split_hi(float a, float b,
                                                  uint32_t& lo_out) {
    __nv_bfloat162 h, l;
    split2(a, h.x, l.x); split2(b, h.y, l.y);
    lo_out = *(uint32_t*)&l;
    return *(uint32_t*)&h;
}
__device__ __forceinline__ float gelu_exact(float v) {
    return 0.5f * v * (1.0f + erff(v * 0.70710678118654752f));
}

// ---------------------------------------------------------------------------
// Embedding
// ---------------------------------------------------------------------------
__global__ __launch_bounds__(256) void embed_kernel(
    const int* __restrict__ ids, const float* __restrict__ tok,
    const float* __restrict__ pos, float* __restrict__ x)
{
    const int row = blockIdx.x;
    const int t   = row & (T - 1);
    const int id  = ids[row];
    const float4* te = (const float4*)(tok + (size_t)id * D);
    const float4* pe = (const float4*)(pos + (size_t)t  * D);
    float4*       xr = (float4*)(x + (size_t)row * D);
    const int c = threadIdx.x;
    float4 a = te[c], b = pe[c];
    xr[c] = make_float4(a.x + b.x, a.y + b.y, a.z + b.z, a.w + b.w);
}

// ---------------------------------------------------------------------------
// LayerNorm
// ---------------------------------------------------------------------------
__device__ __forceinline__ void ln_stats(const float4 v, int tid,
                                         float& mean, float& rstd,
                                         float* r1, float* r2)
{
    float sum = v.x + v.y + v.z + v.w;
    float sq  = v.x * v.x + v.y * v.y + v.z * v.z + v.w * v.w;
    r1[tid] = sum; r2[tid] = sq;
    __syncthreads();
    #pragma unroll
    for (int st = 128; st > 0; st >>= 1) {
        if (tid < st) { r1[tid] += r1[tid + st]; r2[tid] += r2[tid + st]; }
        __syncthreads();
    }
    mean = r1[0] * (1.0f / D);
    const float var = r2[0] * (1.0f / D) - mean * mean;
    rstd = rsqrtf(var + 1e-5f);
}

__global__ __launch_bounds__(256) void ln_kernel(
    const float* __restrict__ x, const float* __restrict__ s,
    const float* __restrict__ b, float* __restrict__ out)
{
    const int row = blockIdx.x, tid = threadIdx.x;
    const float4 v = ((const float4*)(x + (size_t)row * D))[tid];
    __shared__ float r1[256], r2[256];
    float mean, rstd;
    ln_stats(v, tid, mean, rstd, r1, r2);
    const float4 sv = ((const float4*)s)[tid];
    const float4 bv = ((const float4*)b)[tid];
    float4 o;
    o.x = (v.x - mean) * rstd * sv.x + bv.x;
    o.y = (v.y - mean) * rstd * sv.y + bv.y;
    o.z = (v.z - mean) * rstd * sv.z + bv.z;
    o.w = (v.w - mean) * rstd * sv.w + bv.w;
    ((float4*)(out + (size_t)row * D))[tid] = o;
}

__global__ __launch_bounds__(256) void ln_split_kernel(
    const float* __restrict__ x, const float* __restrict__ s,
    const float* __restrict__ b,
    __nv_bfloat16* __restrict__ ah, __nv_bfloat16* __restrict__ al)
{
    const int row = blockIdx.x, tid = threadIdx.x;
    const float4 v = ((const float4*)(x + (size_t)row * D))[tid];
    __shared__ float r1[256], r2[256];
    float mean, rstd;
    ln_stats(v, tid, mean, rstd, r1, r2);
    const float4 sv = ((const float4*)s)[tid];
    const float4 bv = ((const float4*)b)[tid];
    float o[4];
    o[0] = (v.x - mean) * rstd * sv.x + bv.x;
    o[1] = (v.y - mean) * rstd * sv.y + bv.y;
    o[2] = (v.z - mean) * rstd * sv.z + bv.z;
    o[3] = (v.w - mean) * rstd * sv.w + bv.w;
    const size_t base = (size_t)row * D + (tid << 2);
    __nv_bfloat162 h01, h23, l01, l23;
    split2(o[0], h01.x, l01.x); split2(o[1], h01.y, l01.y);
    split2(o[2], h23.x, l23.x); split2(o[3], h23.y, l23.y);
    *(__nv_bfloat162*)(ah + base)     = h01;
    *(__nv_bfloat162*)(ah + base + 2) = h23;
    *(__nv_bfloat162*)(al + base)     = l01;
    *(__nv_bfloat162*)(al + base + 2) = l23;
}

// ---------------------------------------------------------------------------
// Weight prep: W[K,N] fp32 -> hi/lo bf16 [N,K]. 64k x 32n tiles, coalesced
// bf16x2 writes along K.
// ---------------------------------------------------------------------------
__global__ __launch_bounds__(256) void tsplit_kernel(
    const float* __restrict__ W, __nv_bfloat16* __restrict__ oh,
    __nv_bfloat16* __restrict__ ol, int Kd, int Nd)
{
    __shared__ float s[64][33];
    const int n0 = blockIdx.x * 32, k0 = blockIdx.y * 64;
    const int tx = threadIdx.x & 31, ty = threadIdx.x >> 5;
    #pragma unroll
    for (int j = 0; j < 8; j++)
        s[ty + j * 8][tx] = W[(size_t)(k0 + ty + j * 8) * Nd + n0 + tx];
    __syncthreads();
    const int k2 = (threadIdx.x & 31) * 2;
    const int nb = threadIdx.x >> 5;       // 0..7
    #pragma unroll
    for (int pass = 0; pass < 4; pass++) {
        const int n = pass * 8 + nb;
        const float v0 = s[k2][n], v1 = s[k2 + 1][n];
        __nv_bfloat162 h, l;
        split2(v0, h.x, l.x); split2(v1, h.y, l.y);
        const size_t idx = (size_t)(n0 + n) * Kd + k0 + k2;
        *(__nv_bfloat162*)(oh + idx) = h;
        *(__nv_bfloat162*)(ol + idx) = l;
    }
}

// ---------------------------------------------------------------------------
// Warp-MMA GEMM (validated R9): 128x128 tile, BK=64, 3-stage cp.async.
// EPI: 0 fp32, 1 GELU->split bf16, 2 residual add fp32, 3 plain split bf16.
// ---------------------------------------------------------------------------
template <int EPI>
__global__ __launch_bounds__(256) void gemm_mma(
    const __nv_bfloat16* __restrict__ Ah, const __nv_bfloat16* __restrict__ Al,
    const __nv_bfloat16* __restrict__ Bh, const __nv_bfloat16* __restrict__ Bl,
    const float* __restrict__ R, float* __restrict__ Cf,
    __nv_bfloat16* __restrict__ Ch, __nv_bfloat16* __restrict__ Cl,
    int Ndim, int Kdim)
{
    extern __shared__ char smem[];
    const uint32_t sbase = smem_u32(smem);
    const int tid = threadIdx.x, wid = tid >> 5, lane = tid & 31;
    const int row0 = blockIdx.y << 7, col0 = blockIdx.x << 7;
    const int wm = wid & 3, wn = wid >> 2;
    const int nC = Kdim >> 6;

    float acc[2][8][4];
    #pragma unroll
    for (int a = 0; a < 2; a++)
        #pragma unroll
        for (int b = 0; b < 8; b++)
            #pragma unroll
            for (int c = 0; c < 4; c++) acc[a][b][c] = 0.f;

    auto issue = [&](int c) {
        const int s = c % NSTG;
        const int k0 = c << 6;
        const uint32_t sb = sbase + s * STG_B;
        #pragma unroll
        for (int i = 0; i < 16; i++) {
            const int arr = i >> 2;
            const int rem = tid + ((i & 3) << 8);
            const int row = rem >> 3, c16 = rem & 7;
            const uint32_t dst = sb + arr * ARR_B + row * PITCH_B + c16 * 16;
            const __nv_bfloat16* src;
            if (arr == 0)      src = Ah + (size_t)(row0 + row) * Kdim + k0 + c16 * 8;
            else if (arr == 1) src = Al + (size_t)(row0 + row) * Kdim + k0 + c16 * 8;
            else if (arr == 2) src = Bh + (size_t)(col0 + row) * Kdim + k0 + c16 * 8;
            else               src = Bl + (size_t)(col0 + row) * Kdim + k0 + c16 * 8;
            CP16(dst, src);
        }
        CP_COMMIT();
    };

    issue(0);
    if (nC > 1) issue(1);

    for (int c = 0; c < nC; ++c) {
        const int s = c % NSTG;
        if (c + 2 < nC)      { issue(c + 2); CP_WAIT(2); }
        else if (c + 1 < nC) { CP_WAIT(1); }
        else                 { CP_WAIT(0); }
        __syncthreads();

        const uint32_t sa_h = sbase + s * STG_B;
        const uint32_t sa_l = sa_h + ARR_B;
        const uint32_t sb_h = sa_h + 2 * ARR_B;
        const uint32_t sb_l = sa_h + 3 * ARR_B;

        #pragma unroll
        for (int ks = 0; ks < 4; ks++) {
            uint32_t a_h[2][4], a_l[2][4], b_h[8][2], b_l[8][2];
            const uint32_t kb = ks * 32;
            #pragma unroll
            for (int mi = 0; mi < 2; mi++) {
                const int mrow = wm * 32 + mi * 16 + (lane & 15);
                const uint32_t off = mrow * PITCH_B + kb + ((lane >> 4) << 4);
                LDSM4(a_h[mi][0], a_h[mi][1], a_h[mi][2], a_h[mi][3], sa_h + off);
                LDSM4(a_l[mi][0], a_l[mi][1], a_l[mi][2], a_l[mi][3], sa_l + off);
            }
            #pragma unroll
            for (int nb = 0; nb < 4; nb++) {
                const int nrow = wn * 64 + nb * 16 + (((lane >> 4) & 1) << 3) + (lane & 7);
                const uint32_t off = nrow * PITCH_B + kb + (((lane >> 3) & 1) << 4);
                LDSM4(b_h[2 * nb][0], b_h[2 * nb][1],
                      b_h[2 * nb + 1][0], b_h[2 * nb + 1][1], sb_h + off);
                LDSM4(b_l[2 * nb][0], b_l[2 * nb][1],
                      b_l[2 * nb + 1][0], b_l[2 * nb + 1][1], sb_l + off);
            }
            #pragma unroll
            for (int mi = 0; mi < 2; mi++)
                #pragma unroll
                for (int ni = 0; ni < 8; ni++) {
                    MMA_BF16(acc[mi][ni], a_h[mi], b_h[ni]);
                    MMA_BF16(acc[mi][ni], a_h[mi], b_l[ni]);
                    MMA_BF16(acc[mi][ni], a_l[mi], b_h[ni]);
                }
        }
        __syncthreads();
    }

    #pragma unroll
    for (int mi = 0; mi < 2; mi++) {
        #pragma unroll
        for (int ni = 0; ni < 8; ni++) {
            const int r0 = row0 + wm * 32 + mi * 16 + (lane >> 2);
            const int r1 = r0 + 8;
            const int cc = col0 + wn * 64 + ni * 8 + ((lane & 3) << 1);
            const float* a = acc[mi][ni];
            if (EPI == 0) {
                *(float2*)(Cf + (size_t)r0 * Ndim + cc) = make_float2(a[0], a[1]);
                *(float2*)(Cf + (size_t)r1 * Ndim + cc) = make_float2(a[2], a[3]);
            } else if (EPI == 2) {
                const float2 q0 = *(const float2*)(R + (size_t)r0 * Ndim + cc);
                const float2 q1 = *(const float2*)(R + (size_t)r1 * Ndim + cc);
                *(float2*)(Cf + (size_t)r0 * Ndim + cc) = make_float2(a[0] + q0.x, a[1] + q0.y);
                *(float2*)(Cf + (size_t)r1 * Ndim + cc) = make_float2(a[2] + q1.x, a[3] + q1.y);
            } else {
                float v0 = a[0], v1 = a[1], v2 = a[2], v3 = a[3];
                if (EPI == 1) { v0 = gelu_exact(v0); v1 = gelu_exact(v1);
                                v2 = gelu_exact(v2); v3 = gelu_exact(v3); }
                __nv_bfloat162 h0, l0, h1, l1;
                split2(v0, h0.x, l0.x); split2(v1, h0.y, l0.y);
                split2(v2, h1.x, l1.x); split2(v3, h1.y, l1.y);
                *(__nv_bfloat162*)(Ch + (size_t)r0 * Ndim + cc) = h0;
                *(__nv_bfloat162*)(Cl + (size_t)r0 * Ndim + cc) = l0;
                *(__nv_bfloat162*)(Ch + (size_t)r1 * Ndim + cc) = h1;
                *(__nv_bfloat162*)(Cl + (size_t)r1 * Ndim + cc) = l1;
            }
        }
    }
}

// ---------------------------------------------------------------------------
// Flash attention: fused scores + causal softmax + PV. Q block 128 rows,
// KV tiles of 64 keys, online softmax, 3-term bf16 split throughout.
// 8 warps, each owns 16 full rows (row reductions stay inside the warp).
// ---------------------------------------------------------------------------
__global__ __launch_bounds__(256) void flash_mma(
    const __nv_bfloat16* __restrict__ qh, const __nv_bfloat16* __restrict__ ql,
    __nv_bfloat16* __restrict__ oh, __nv_bfloat16* __restrict__ ol)
{
    extern __shared__ char smem[];
    const uint32_t sbase = smem_u32(smem);
    const int it = gridDim.x - 1 - blockIdx.x;          // heavy CTAs first
    const int bh = blockIdx.y, b = bh >> 4, h = bh & 15;
    const int tid = threadIdx.x, wid = tid >> 5, lane = tid & 31;

    const uint32_t sQh = sbase, sQl = sbase + QARR;
    const uint32_t kv0 = sbase + 2 * QARR;

    const size_t qbase = ((size_t)b * T + it * 128) * D3 + h * DH;
    const int nT = 2 * it + 2;

    // Q load (once) + KV tile 0, one group
    #pragma unroll
    for (int i = 0; i < 8; i++) {
        const int arr = i >> 2;                         // 0=hi, 1=lo
        const int rem = tid + ((i & 3) << 8);
        const int row = rem >> 3, c16 = rem & 7;
        const __nv_bfloat16* src = (arr ? ql : qh) + qbase + (size_t)row * D3 + c16 * 8;
        CP16(sbase + arr * QARR + row * APITCH + c16 * 16, src);
    }
    auto issueKV = [&](int jt) {
        const uint32_t sb = kv0 + (jt & 1) * KVSTG;
        const size_t kbase = ((size_t)b * T + jt * 64) * D3 + D + h * DH;
        const size_t vbase = kbase + D;
        #pragma unroll
        for (int i = 0; i < 8; i++) {
            const int arr = i >> 1;                     // Kh,Kl,Vh,Vl
            const int rem = tid + ((i & 1) << 8);
            const int row = rem >> 3, c16 = rem & 7;
            const __nv_bfloat16* src;
            if (arr == 0)      src = qh + kbase + (size_t)row * D3 + c16 * 8;
            else if (arr == 1) src = ql + kbase + (size_t)row * D3 + c16 * 8;
            else if (arr == 2) src = qh + vbase + (size_t)row * D3 + c16 * 8;
            else               src = ql + vbase + (size_t)row * D3 + c16 * 8;
            CP16(sb + arr * AARR + row * APITCH + c16 * 16, src);
        }
    };
    issueKV(0);
    CP_COMMIT();

    float m0 = -CUDART_INF_F, m1 = -CUDART_INF_F, l0 = 0.f, l1 = 0.f;
    float acc_o[8][4];
    #pragma unroll
    for (int ni = 0; ni < 8; ni++)
        #pragma unroll
        for (int j = 0; j < 4; j++) acc_o[ni][j] = 0.f;

    const int rloc0 = wid * 16 + (lane >> 2);
    const int row_g0 = it * 128 + rloc0;
    const int row_g1 = row_g0 + 8;

    for (int jt = 0; jt < nT; ++jt) {
        if (jt + 1 < nT) { issueKV(jt + 1); CP_COMMIT(); CP_WAIT(1); }
        else             { CP_WAIT(0); }
        __syncthreads();

        const uint32_t sKh = kv0 + (jt & 1) * KVSTG;
        const uint32_t sKl = sKh + AARR;
        const uint32_t sVh = sKh + 2 * AARR;
        const uint32_t sVl = sKh + 3 * AARR;

        // --- S = Q . K^T (3-term split) ---
        float accs[8][4];
        #pragma unroll
        for (int ni = 0; ni < 8; ni++)
            #pragma unroll
            for (int j = 0; j < 4; j++) accs[ni][j] = 0.f;

        #pragma unroll
        for (int ks = 0; ks < 4; ks++) {
            const uint32_t kb = ks * 32;
            uint32_t a_h[4], a_l[4], b_h[8][2], b_l[8][2];
            const uint32_t aoff = (wid * 16 + (lane & 15)) * APITCH + kb + ((lane >> 4) << 4);
            LDSM4(a_h[0], a_h[1], a_h[2], a_h[3], sQh + aoff);
            LDSM4(a_l[0], a_l[1], a_l[2], a_l[3], sQl + aoff);
            #pragma unroll
            for (int nb = 0; nb < 4; nb++) {
                const int nrow = nb * 16 + (((lane >> 4) & 1) << 3) + (lane & 7);
                const uint32_t off = nrow * APITCH + kb + (((lane >> 3) & 1) << 4);
                LDSM4(b_h[2 * nb][0], b_h[2 * nb][1],
                      b_h[2 * nb + 1][0], b_h[2 * nb + 1][1], sKh + off);
                LDSM4(b_l[2 * nb][0], b_l[2 * nb][1],
                      b_l[2 * nb + 1][0], b_l[2 * nb + 1][1], sKl + off);
            }
            #pragma unroll
            for (int ni = 0; ni < 8; ni++) {
                MMA_BF16(accs[ni], a_h, b_h[ni]);
                MMA_BF16(accs[ni], a_h, b_l[ni]);
                MMA_BF16(accs[ni], a_l, b_h[ni]);
            }
        }

        // --- scale + causal mask (only last two tiles touch the diagonal) ---
        const bool need_mask = (jt >= 2 * it);
        #pragma unroll
        for (int ni = 0; ni < 8; ni++) {
            const int c0 = jt * 64 + ni * 8 + ((lane & 3) << 1);
            #pragma unroll
            for (int j = 0; j < 4; j++) {
                float v = accs[ni][j] * 0.125f;
                if (need_mask) {
                    const int col = c0 + (j & 1);
                    const int row = (j < 2) ? row_g0 : row_g1;
                    if (col > row) v = -CUDART_INF_F;
                }
                accs[ni][j] = v;
            }
        }

        // --- online softmax: row max / exp / row sum (warp-local) ---
        float mx0 = -CUDART_INF_F, mx1 = -CUDART_INF_F;
        #pragma unroll
        for (int ni = 0; ni < 8; ni++) {
            mx0 = fmaxf(mx0, fmaxf(accs[ni][0], accs[ni][1]));
            mx1 = fmaxf(mx1, fmaxf(accs[ni][2], accs[ni][3]));
        }
        mx0 = fmaxf(mx0, __shfl_xor_sync(0xffffffffu, mx0, 1));
        mx0 = fmaxf(mx0, __shfl_xor_sync(0xffffffffu, mx0, 2));
        mx1 = fmaxf(mx1, __shfl_xor_sync(0xffffffffu, mx1, 1));
        mx1 = fmaxf(mx1, __shfl_xor_sync(0xffffffffu, mx1, 2));
        const float nm0 = fmaxf(m0, mx0), nm1 = fmaxf(m1, mx1);
        const float al0 = expf(m0 - nm0), al1 = expf(m1 - nm1);

        float s0 = 0.f, s1 = 0.f;
        #pragma unroll
        for (int ni = 0; ni < 8; ni++) {
            accs[ni][0] = expf(accs[ni][0] - nm0);
            accs[ni][1] = expf(accs[ni][1] - nm0);
            accs[ni][2] = expf(accs[ni][2] - nm1);
            accs[ni][3] = expf(accs[ni][3] - nm1);
            s0 += accs[ni][0] + accs[ni][1];
            s1 += accs[ni][2] + accs[ni][3];
        }
        s0 += __shfl_xor_sync(0xffffffffu, s0, 1);
        s0 += __shfl_xor_sync(0xffffffffu, s0, 2);
        s1 += __shfl_xor_sync(0xffffffffu, s1, 1);
        s1 += __shfl_xor_sync(0xffffffffu, s1, 2);
        l0 = l0 * al0 + s0; l1 = l1 * al1 + s1;
        m0 = nm0; m1 = nm1;

        // --- rescale O, then O += P . V ---
        #pragma unroll
        for (int ni = 0; ni < 8; ni++) {
            acc_o[ni][0] *= al0; acc_o[ni][1] *= al0;
            acc_o[ni][2] *= al1; acc_o[ni][3] *= al1;
        }
        #pragma unroll
        for (int ks = 0; ks < 4; ks++) {
            // P fragment for k-block ks from S fragments 2ks, 2ks+1
            uint32_t pa_h[4], pa_l[4];
            pa_h[0] = pack_split_hi(accs[2*ks][0],   accs[2*ks][1],   pa_l[0]);
            pa_h[1] = pack_split_hi(accs[2*ks][2],   accs[2*ks][3],   pa_l[1]);
            pa_h[2] = pack_split_hi(accs[2*ks+1][0], accs[2*ks+1][1], pa_l[2]);
            pa_h[3] = pack_split_hi(accs[2*ks+1][2], accs[2*ks+1][3], pa_l[3]);

            uint32_t vb_h[8][2], vb_l[8][2];
            #pragma unroll
            for (int nb = 0; nb < 4; nb++) {
                const uint32_t off = (ks * 16 + (lane & 15)) * APITCH
                                   + (nb * 16) * 2 + ((lane >> 4) << 4);
                LDSM4T(vb_h[2 * nb][0], vb_h[2 * nb][1],
                       vb_h[2 * nb + 1][0], vb_h[2 * nb + 1][1], sVh + off);
                LDSM4T(vb_l[2 * nb][0], vb_l[2 * nb][1],
                       vb_l[2 * nb + 1][0], vb_l[2 * nb + 1][1], sVl + off);
            }
            #pragma unroll
            for (int ni = 0; ni < 8; ni++) {
                MMA_BF16(acc_o[ni], pa_h, vb_h[ni]);
                MMA_BF16(acc_o[ni], pa_h, vb_l[ni]);
                MMA_BF16(acc_o[ni], pa_l, vb_h[ni]);
            }
        }
        __syncthreads();
    }

    // --- epilogue: O / l, split-bf16 store ---
    const float inv0 = 1.0f / l0, inv1 = 1.0f / l1;
    #pragma unroll
    for (int ni = 0; ni < 8; ni++) {
        const int cc = h * DH + ni * 8 + ((lane & 3) << 1);
        const size_t g0 = ((size_t)b * T + row_g0) * D + cc;
        const size_t g1 = ((size_t)b * T + row_g1) * D + cc;
        __nv_bfloat162 h0, lo0, h1, lo1;
        split2(acc_o[ni][0] * inv0, h0.x, lo0.x);
        split2(acc_o[ni][1] * inv0, h0.y, lo0.y);
        split2(acc_o[ni][2] * inv1, h1.x, lo1.x);
        split2(acc_o[ni][3] * inv1, h1.y, lo1.y);
        *(__nv_bfloat162*)(oh + g0) = h0;
        *(__nv_bfloat162*)(ol + g0) = lo0;
        *(__nv_bfloat162*)(oh + g1) = h1;
        *(__nv_bfloat162*)(ol + g1) = lo1;
    }
}

// ---------------------------------------------------------------------------
// Launcher
// ---------------------------------------------------------------------------
extern "C" void kernel_launch(void* const* d_in, const int* in_sizes, int n_in,
                              void* d_out, int out_size)
{
    const int*   ids   = (const int*)  d_in[0];
    const float* tok   = (const float*)d_in[1];
    const float* pos   = (const float*)d_in[2];
    const float* ln1_s = (const float*)d_in[3];
    const float* ln1_b = (const float*)d_in[4];
    const float* Wqkv  = (const float*)d_in[5];
    const float* Wout  = (const float*)d_in[6];
    const float* ln2_s = (const float*)d_in[7];
    const float* ln2_b = (const float*)d_in[8];
    const float* W1    = (const float*)d_in[9];
    const float* W2    = (const float*)d_in[10];
    const float* lnf_s = (const float*)d_in[11];
    const float* lnf_b = (const float*)d_in[12];
    float* out = (float*)d_out;

    float *x;
    __nv_bfloat16 *qh, *ql, *ah, *al, *bh, *bl;
    __nv_bfloat16 *wqh, *wql, *woh, *wol, *w1h, *w1l, *w2h, *w2l;
    cudaGetSymbolAddress((void**)&x,   g_x);
    cudaGetSymbolAddress((void**)&qh,  g_qh);
    cudaGetSymbolAddress((void**)&ql,  g_ql);
    cudaGetSymbolAddress((void**)&ah,  g_ah);
    cudaGetSymbolAddress((void**)&al,  g_al);
    cudaGetSymbolAddress((void**)&bh,  g_bh);
    cudaGetSymbolAddress((void**)&bl,  g_bl);
    cudaGetSymbolAddress((void**)&wqh, g_wqkv_h);
    cudaGetSymbolAddress((void**)&wql, g_wqkv_l);
    cudaGetSymbolAddress((void**)&woh, g_wout_h);
    cudaGetSymbolAddress((void**)&wol, g_wout_l);
    cudaGetSymbolAddress((void**)&w1h, g_w1_h);
    cudaGetSymbolAddress((void**)&w1l, g_w1_l);
    cudaGetSymbolAddress((void**)&w2h, g_w2_h);
    cudaGetSymbolAddress((void**)&w2l, g_w2_l);

    cudaFuncSetAttribute(gemm_mma<0>, cudaFuncAttributeMaxDynamicSharedMemorySize, GEMM_SMEM);
    cudaFuncSetAttribute(gemm_mma<1>, cudaFuncAttributeMaxDynamicSharedMemorySize, GEMM_SMEM);
    cudaFuncSetAttribute(gemm_mma<2>, cudaFuncAttributeMaxDynamicSharedMemorySize, GEMM_SMEM);
    cudaFuncSetAttribute(gemm_mma<3>, cudaFuncAttributeMaxDynamicSharedMemorySize, GEMM_SMEM);
    cudaFuncSetAttribute(flash_mma,   cudaFuncAttributeMaxDynamicSharedMemorySize, FL_SMEM);

    for (int l = 0; l < Lx; l++) {
        tsplit_kernel<<<dim3(D3 / 32, D / 64),  256>>>(Wqkv + (size_t)l * D * D3,
            wqh + (size_t)l * D3 * D,  wql + (size_t)l * D3 * D,  D,  D3);
        tsplit_kernel<<<dim3(D / 32, D / 64),   256>>>(Wout + (size_t)l * D * D,
            woh + (size_t)l * D * D,   wol + (size_t)l * D * D,   D,  D);
        tsplit_kernel<<<dim3(DFF / 32, D / 64), 256>>>(W1 + (size_t)l * D * DFF,
            w1h + (size_t)l * DFF * D, w1l + (size_t)l * DFF * D, D,  DFF);
        tsplit_kernel<<<dim3(D / 32, DFF / 64), 256>>>(W2 + (size_t)l * DFF * D,
            w2h + (size_t)l * D * DFF, w2l + (size_t)l * D * DFF, DFF, D);
    }

    embed_kernel<<<MR, 256>>>(ids, tok, pos, x);

    for (int l = 0; l < Lx; l++) {
        ln_split_kernel<<<MR, 256>>>(x, ln1_s + l * D, ln1_b + l * D, ah, al);
        gemm_mma<3><<<dim3(D3 / 128, MR / 128), 256, GEMM_SMEM>>>(
            ah, al, wqh + (size_t)l * D3 * D, wql + (size_t)l * D3 * D,
            nullptr, nullptr, qh, ql, D3, D);

        flash_mma<<<dim3(T / 128, Bx * H), 256, FL_SMEM>>>(qh, ql, ah, al);

        gemm_mma<2><<<dim3(D / 128, MR / 128), 256, GEMM_SMEM>>>(
            ah, al, woh + (size_t)l * D * D, wol + (size_t)l * D * D,
            x, x, nullptr, nullptr, D, D);

        ln_split_kernel<<<MR, 256>>>(x, ln2_s + l * D, ln2_b + l * D, ah, al);
        gemm_mma<1><<<dim3(DFF / 128, MR / 128), 256, GEMM_SMEM>>>(
            ah, al, w1h + (size_t)l * DFF * D, w1l + (size_t)l * DFF * D,
            nullptr, nullptr, bh, bl, DFF, D);
        gemm_mma<2><<<dim3(D / 128, MR / 128), 256, GEMM_SMEM>>>(
            bh, bl, w2h + (size_t)l * D * DFF, w2l + (size_t)l * D * DFF,
            x, x, nullptr, nullptr, D, DFF);
    }

    ln_kernel<<<MR, 256>>>(x, lnf_s, lnf_b, out);
}